// round 4
// baseline (speedup 1.0000x reference)
#include <cuda_runtime.h>
#include <cstdint>

// MusicRNN: 2-layer LSTM (B=2048, T=256, I=88, H=64) + FC(64->13)
//   K1: precompute layer-0 input projection P0 (gate-interleaved float4).
//       Coalesced global loads + padded SMEM transpose (no 32-way conflicts).
//   K2: persistent fused recurrence. 128 CTAs x 256 threads (2 warps/SMSP),
//       K-SPLIT across half-warps: lanes 0-15 sum k=0..31, lanes 16-31 sum
//       k=32..63, combined via shfl.bfly(16)+add.f32x2. Crossbar traffic stays
//       at RG=2 level while warp count doubles. Weights in SMEM (gate-packed
//       float4, row stride 65), h via SMEM double buffer, c in registers.

#define BB 2048
#define TT 256
#define II 88
#define HH 64
#define OO 13

__device__ float4 g_P0[(size_t)TT * BB * HH];   // [T][B][H] gate pre-acts

typedef unsigned long long ull;

// ---------------- packed f32x2 helpers ----------------
__device__ __forceinline__ ull pack2(float lo, float hi) {
    ull r; asm("mov.b64 %0, {%1, %2};" : "=l"(r) : "f"(lo), "f"(hi)); return r;
}
__device__ __forceinline__ ull dup2(float v) {
    ull r; asm("mov.b64 %0, {%1, %1};" : "=l"(r) : "f"(v)); return r;
}
__device__ __forceinline__ void unpack2(ull v, float& lo, float& hi) {
    asm("mov.b64 {%0, %1}, %2;" : "=f"(lo), "=f"(hi) : "l"(v));
}
__device__ __forceinline__ void fma2(ull& d, ull a, ull b) {
    asm("fma.rn.f32x2 %0, %1, %2, %0;" : "+l"(d) : "l"(a), "l"(b));
}
__device__ __forceinline__ ull add2(ull a, ull b) {
    ull r; asm("add.rn.f32x2 %0, %1, %2;" : "=l"(r) : "l"(a), "l"(b)); return r;
}
// butterfly-16 exchange + add (combines the two k-halves of a warp)
__device__ __forceinline__ ull bfly16_add(ull v) {
    unsigned lo, hi, lo2, hi2;
    asm("mov.b64 {%0, %1}, %2;" : "=r"(lo), "=r"(hi) : "l"(v));
    asm("shfl.sync.bfly.b32 %0, %1, 16, 0x1f, 0xffffffff;" : "=r"(lo2) : "r"(lo));
    asm("shfl.sync.bfly.b32 %0, %1, 16, 0x1f, 0xffffffff;" : "=r"(hi2) : "r"(hi));
    ull o; asm("mov.b64 %0, {%1, %2};" : "=l"(o) : "r"(lo2), "r"(hi2));
    return add2(v, o);
}

// ---------------- activations (MUFU-based, ~1e-7 rel err) ----------------
__device__ __forceinline__ float sigf(float x) {
    return __fdividef(1.0f, 1.0f + __expf(-x));
}
__device__ __forceinline__ float tanhf_fast(float x) {
    return __fdividef(2.0f, 1.0f + __expf(-2.0f * x)) - 1.0f;
}

__device__ __forceinline__ void lstm_act_pair(
    ull aI, ull aF, ull aG, ull aO, float* c, float* hn, int r)
{
    float i0, i1, f0, f1, g0, g1, o0, o1;
    unpack2(aI, i0, i1); unpack2(aF, f0, f1);
    unpack2(aG, g0, g1); unpack2(aO, o0, o1);
    float cc0 = sigf(f0) * c[r]     + sigf(i0) * tanhf_fast(g0);
    float cc1 = sigf(f1) * c[r + 1] + sigf(i1) * tanhf_fast(g1);
    c[r]      = cc0;  hn[r]     = sigf(o0) * tanhf_fast(cc0);
    c[r + 1]  = cc1;  hn[r + 1] = sigf(o1) * tanhf_fast(cc1);
}

// =====================================================================
// K1: input projection.  Grid: B*T/64 CTAs, 512 threads.
//     Weight SMEM row stride 65 float4 (fill: 4-way conflict max);
//     xs row stride 66 floats (fill: 2-way conflict max). All LDG coalesced.
// =====================================================================
#define K1_W4   (II * 65)                 // 5720 float4
#define K1_SMEM ((K1_W4 + 64) * 16 + II * 66 * 4)   // 115776 B

__global__ void __launch_bounds__(512) k1_inproj(
    const float* __restrict__ x, const float* __restrict__ w_ih0,
    const float* __restrict__ b_ih0, const float* __restrict__ b_hh0)
{
    extern __shared__ float4 sm4[];
    float4* w0p = sm4;                       // [88][65] gate-packed (padded)
    float4* b0p = sm4 + K1_W4;               // [64]
    float*  xs  = (float*)(sm4 + K1_W4 + 64);   // [88][66] k-major (padded)
    float*  ws  = (float*)w0p;

    const int tid = threadIdx.x;

    // coalesced weight load + padded transpose:  w_ih0 is [256][88]
    for (int idx = tid; idx < 256 * II; idx += 512) {
        int g = idx / II, k = idx - g * II;
        int h = g & 63, gate = g >> 6;
        ws[(k * 65 + h) * 4 + gate] = w_ih0[idx];
    }
    if (tid < HH) {
        float4 v;
        v.x = b_ih0[tid]       + b_hh0[tid];
        v.y = b_ih0[tid +  64] + b_hh0[tid +  64];
        v.z = b_ih0[tid + 128] + b_hh0[tid + 128];
        v.w = b_ih0[tid + 192] + b_hh0[tid + 192];
        b0p[tid] = v;
    }
    const int bt0 = blockIdx.x * 64;   // 64 consecutive (b*T+t) rows
    for (int idx = tid; idx < 64 * II; idx += 512) {
        int r = idx / II, k = idx - r * II;
        xs[k * 66 + r] = x[(size_t)bt0 * II + idx];
    }
    __syncthreads();

    const int h  = tid & 63;
    const int r0 = (tid >> 6) * 8;   // 8 rows per thread

    ull aI[4], aF[4], aG[4], aO[4];
    {
        float4 bv = b0p[h];
        #pragma unroll
        for (int p = 0; p < 4; p++) {
            aI[p] = dup2(bv.x); aF[p] = dup2(bv.y);
            aG[p] = dup2(bv.z); aO[p] = dup2(bv.w);
        }
    }
    #pragma unroll 4
    for (int k = 0; k < II; k++) {
        float4 w = w0p[k * 65 + h];
        ull wi = dup2(w.x), wf = dup2(w.y), wg = dup2(w.z), wo = dup2(w.w);
        const ull* hv = (const ull*)&xs[k * 66 + r0];   // broadcast loads
        ull v0 = hv[0], v1 = hv[1], v2 = hv[2], v3 = hv[3];
        fma2(aI[0], wi, v0); fma2(aI[1], wi, v1); fma2(aI[2], wi, v2); fma2(aI[3], wi, v3);
        fma2(aF[0], wf, v0); fma2(aF[1], wf, v1); fma2(aF[2], wf, v2); fma2(aF[3], wf, v3);
        fma2(aG[0], wg, v0); fma2(aG[1], wg, v1); fma2(aG[2], wg, v2); fma2(aG[3], wg, v3);
        fma2(aO[0], wo, v0); fma2(aO[1], wo, v1); fma2(aO[2], wo, v2); fma2(aO[3], wo, v3);
    }
    #pragma unroll
    for (int p = 0; p < 4; p++) {
        float i0, i1, f0, f1, g0, g1, o0, o1;
        unpack2(aI[p], i0, i1); unpack2(aF[p], f0, f1);
        unpack2(aG[p], g0, g1); unpack2(aO[p], o0, o1);
        int bt = bt0 + r0 + 2 * p;
        int t = bt & (TT - 1), b = bt >> 8;
        g_P0[((size_t)t * BB + b) * HH + h] = make_float4(i0, f0, g0, o0);
        bt++; t = bt & (TT - 1); b = bt >> 8;
        g_P0[((size_t)t * BB + b) * HH + h] = make_float4(i1, f1, g1, o1);
    }
}

// =====================================================================
// K2: persistent fused recurrence + FC.
//     256 threads: warp w = [rg = w>>2][hb = w&3]; lane = [kh = l>>4][hl = l&15]
//     h = hb*16+hl owns 4 gates x 8 rows (r0 = rg*8), summing k-half kh.
// =====================================================================
#define K2_W4   (HH * 65)                        // 4160 float4 per matrix
#define K2_SMEM ((3 * K2_W4 + 64) * 16 + (2048 + 1024) * 4)   // 212992 B

__global__ void __launch_bounds__(256) k2_rnn(
    const float* __restrict__ w_hh0, const float* __restrict__ w_ih1,
    const float* __restrict__ w_hh1, const float* __restrict__ b_ih1,
    const float* __restrict__ b_hh1, const float* __restrict__ fc_w,
    const float* __restrict__ fc_b, float* __restrict__ out)
{
    extern __shared__ float4 sm4[];
    float4* w0p = sm4;                     // [64][65] gate-packed W_hh0
    float4* w1i = sm4 + K2_W4;             // W_ih1
    float4* w1h = sm4 + 2 * K2_W4;         // W_hh1
    float4* b1p = sm4 + 3 * K2_W4;         // [64]
    float*  h0buf = (float*)(sm4 + 3 * K2_W4 + 64);  // 2 x [64][16]
    float*  h1s   = h0buf + 2048;                    // [64][16]

    const int tid = threadIdx.x;

    // coalesced weight loads + padded transpose: each matrix is [256][64]
    {
        float* s0 = (float*)w0p; float* s1 = (float*)w1i; float* s2 = (float*)w1h;
        for (int idx = tid; idx < 256 * HH; idx += 256) {
            int g = idx >> 6, k = idx & 63;
            int h = g & 63, gate = g >> 6;
            int sidx = (k * 65 + h) * 4 + gate;
            s0[sidx] = w_hh0[idx];
            s1[sidx] = w_ih1[idx];
            s2[sidx] = w_hh1[idx];
        }
    }
    if (tid < HH) {
        float4 v;
        v.x = b_ih1[tid]       + b_hh1[tid];
        v.y = b_ih1[tid +  64] + b_hh1[tid +  64];
        v.z = b_ih1[tid + 128] + b_hh1[tid + 128];
        v.w = b_ih1[tid + 192] + b_hh1[tid + 192];
        b1p[tid] = v;
    }
    for (int idx = tid; idx < 3072; idx += 256) h0buf[idx] = 0.0f;
    __syncthreads();

    const int lane = tid & 31;
    const int kh   = lane >> 4;                       // k-half: 0 or 1
    const int h    = ((tid >> 5) & 3) * 16 + (lane & 15);
    const int r0   = (tid >> 7) * 8;                  // rowgroup: rows r0..r0+7
    const int kb   = kh * 32;                         // k base for this half
    const int bR0  = blockIdx.x * 16;

    float c0[8], c1[8];
    #pragma unroll
    for (int r = 0; r < 8; r++) { c0[r] = 0.0f; c1[r] = 0.0f; }

    // P0 prefetch (kh==0 lanes only; kh==1 accs init to zero)
    float4 xg[8];
    if (kh == 0) {
        #pragma unroll
        for (int j = 0; j < 8; j++)
            xg[j] = g_P0[(size_t)(bR0 + r0 + j) * HH + h];
    }

    for (int t = 0; t < TT; t++) {
        ull aI[4], aF[4], aG[4], aO[4];
        if (kh == 0) {
            #pragma unroll
            for (int p = 0; p < 4; p++) {
                aI[p] = pack2(xg[2 * p].x, xg[2 * p + 1].x);
                aF[p] = pack2(xg[2 * p].y, xg[2 * p + 1].y);
                aG[p] = pack2(xg[2 * p].z, xg[2 * p + 1].z);
                aO[p] = pack2(xg[2 * p].w, xg[2 * p + 1].w);
            }
            // prefetch P0 for t+1 (overlaps layer-0 matvec)
            int tn = (t + 1 < TT) ? (t + 1) : t;
            size_t base = ((size_t)tn * BB + bR0 + r0) * HH + h;
            #pragma unroll
            for (int j = 0; j < 8; j++) xg[j] = g_P0[base + (size_t)j * HH];
        } else {
            #pragma unroll
            for (int p = 0; p < 4; p++) { aI[p] = 0; aF[p] = 0; aG[p] = 0; aO[p] = 0; }
        }

        // ---- layer 0: gates += h0(t-1) @ W_hh0^T  (this thread's k-half) ----
        const float* hp = h0buf + (t & 1) * 1024;
        #pragma unroll 8
        for (int k = 0; k < 32; k++) {
            int kk = kb + k;
            float4 w = w0p[kk * 65 + h];
            ull wi = dup2(w.x), wf = dup2(w.y), wg = dup2(w.z), wo = dup2(w.w);
            const ull* hv = (const ull*)(hp + (kk << 4) + r0);
            ull v0 = hv[0], v1 = hv[1], v2 = hv[2], v3 = hv[3];
            fma2(aI[0], wi, v0); fma2(aI[1], wi, v1); fma2(aI[2], wi, v2); fma2(aI[3], wi, v3);
            fma2(aF[0], wf, v0); fma2(aF[1], wf, v1); fma2(aF[2], wf, v2); fma2(aF[3], wf, v3);
            fma2(aG[0], wg, v0); fma2(aG[1], wg, v1); fma2(aG[2], wg, v2); fma2(aG[3], wg, v3);
            fma2(aO[0], wo, v0); fma2(aO[1], wo, v1); fma2(aO[2], wo, v2); fma2(aO[3], wo, v3);
        }
        // combine k-halves
        #pragma unroll
        for (int p = 0; p < 4; p++) {
            aI[p] = bfly16_add(aI[p]); aF[p] = bfly16_add(aF[p]);
            aG[p] = bfly16_add(aG[p]); aO[p] = bfly16_add(aO[p]);
        }
        float h0n[8];
        #pragma unroll
        for (int p = 0; p < 4; p++)
            lstm_act_pair(aI[p], aF[p], aG[p], aO[p], c0, h0n, 2 * p);

        if (kh == 0) {
            float* hw = h0buf + ((t + 1) & 1) * 1024 + (h << 4) + r0;
            *(float4*)hw       = make_float4(h0n[0], h0n[1], h0n[2], h0n[3]);
            *((float4*)hw + 1) = make_float4(h0n[4], h0n[5], h0n[6], h0n[7]);
        }
        __syncthreads();

        // ---- layer 1: gates = b1 + h0(t) @ W_ih1^T + h1(t-1) @ W_hh1^T ----
        if (kh == 0) {
            float4 bv = b1p[h];
            #pragma unroll
            for (int p = 0; p < 4; p++) {
                aI[p] = dup2(bv.x); aF[p] = dup2(bv.y);
                aG[p] = dup2(bv.z); aO[p] = dup2(bv.w);
            }
        } else {
            #pragma unroll
            for (int p = 0; p < 4; p++) { aI[p] = 0; aF[p] = 0; aG[p] = 0; aO[p] = 0; }
        }
        const float* h0c = h0buf + ((t + 1) & 1) * 1024;
        #pragma unroll 4
        for (int k = 0; k < 32; k++) {
            int kk = kb + k;
            float4 wa = w1i[kk * 65 + h];
            float4 wb = w1h[kk * 65 + h];
            const ull* av = (const ull*)(h0c + (kk << 4) + r0);
            const ull* uv = (const ull*)(h1s + (kk << 4) + r0);
            ull a0 = av[0], a1 = av[1], a2 = av[2], a3 = av[3];
            ull u0 = uv[0], u1 = uv[1], u2 = uv[2], u3 = uv[3];
            ull wi = dup2(wa.x), wf = dup2(wa.y), wg = dup2(wa.z), wo = dup2(wa.w);
            fma2(aI[0], wi, a0); fma2(aI[1], wi, a1); fma2(aI[2], wi, a2); fma2(aI[3], wi, a3);
            fma2(aF[0], wf, a0); fma2(aF[1], wf, a1); fma2(aF[2], wf, a2); fma2(aF[3], wf, a3);
            fma2(aG[0], wg, a0); fma2(aG[1], wg, a1); fma2(aG[2], wg, a2); fma2(aG[3], wg, a3);
            fma2(aO[0], wo, a0); fma2(aO[1], wo, a1); fma2(aO[2], wo, a2); fma2(aO[3], wo, a3);
            wi = dup2(wb.x); wf = dup2(wb.y); wg = dup2(wb.z); wo = dup2(wb.w);
            fma2(aI[0], wi, u0); fma2(aI[1], wi, u1); fma2(aI[2], wi, u2); fma2(aI[3], wi, u3);
            fma2(aF[0], wf, u0); fma2(aF[1], wf, u1); fma2(aF[2], wf, u2); fma2(aF[3], wf, u3);
            fma2(aG[0], wg, u0); fma2(aG[1], wg, u1); fma2(aG[2], wg, u2); fma2(aG[3], wg, u3);
            fma2(aO[0], wo, u0); fma2(aO[1], wo, u1); fma2(aO[2], wo, u2); fma2(aO[3], wo, u3);
        }
        #pragma unroll
        for (int p = 0; p < 4; p++) {
            aI[p] = bfly16_add(aI[p]); aF[p] = bfly16_add(aF[p]);
            aG[p] = bfly16_add(aG[p]); aO[p] = bfly16_add(aO[p]);
        }
        float h1n[8];
        #pragma unroll
        for (int p = 0; p < 4; p++)
            lstm_act_pair(aI[p], aF[p], aG[p], aO[p], c1, h1n, 2 * p);

        __syncthreads();   // all reads of h1s(t-1) done before overwrite
        if (kh == 0) {
            float* hw1 = h1s + (h << 4) + r0;
            *(float4*)hw1       = make_float4(h1n[0], h1n[1], h1n[2], h1n[3]);
            *((float4*)hw1 + 1) = make_float4(h1n[4], h1n[5], h1n[6], h1n[7]);
        }
    }
    __syncthreads();

    // ---- FC head: out[b][o] = h1 . fc_w[o] + fc_b[o] ----
    for (int idx = tid; idx < 16 * OO; idx += 256) {
        int o = idx >> 4, r = idx & 15;
        float s = fc_b[o];
        #pragma unroll 8
        for (int k = 0; k < HH; k++)
            s += fc_w[o * HH + k] * h1s[(k << 4) + r];
        out[(size_t)(bR0 + r) * OO + o] = s;
    }
}

// =====================================================================
extern "C" void kernel_launch(void* const* d_in, const int* in_sizes, int n_in,
                              void* d_out, int out_size)
{
    (void)in_sizes; (void)n_in; (void)out_size;
    const float* x     = (const float*)d_in[0];
    const float* w_ih0 = (const float*)d_in[1];
    const float* w_hh0 = (const float*)d_in[2];
    const float* b_ih0 = (const float*)d_in[3];
    const float* b_hh0 = (const float*)d_in[4];
    const float* w_ih1 = (const float*)d_in[5];
    const float* w_hh1 = (const float*)d_in[6];
    const float* b_ih1 = (const float*)d_in[7];
    const float* b_hh1 = (const float*)d_in[8];
    const float* fc_w  = (const float*)d_in[9];
    const float* fc_b  = (const float*)d_in[10];
    float* out = (float*)d_out;

    cudaFuncSetAttribute(k1_inproj, cudaFuncAttributeMaxDynamicSharedMemorySize, K1_SMEM);
    cudaFuncSetAttribute(k2_rnn,    cudaFuncAttributeMaxDynamicSharedMemorySize, K2_SMEM);

    k1_inproj<<<(BB * TT) / 64, 512, K1_SMEM>>>(x, w_ih0, b_ih0, b_hh0);
    k2_rnn<<<BB / 16, 256, K2_SMEM>>>(w_hh0, w_ih1, w_hh1, b_ih1, b_hh1,
                                      fc_w, fc_b, out);
}

// round 5
// speedup vs baseline: 1.5070x; 1.5070x over previous
#include <cuda_runtime.h>
#include <cuda_bf16.h>
#include <cstdint>

// MusicRNN: 2-layer LSTM (B=2048, T=256, I=88, H=64) + FC(64->13)
//   K1: fp32 input projection P0 (proven, unchanged).
//   K2: tensor-core recurrence. 128 CTAs x 512 threads (16 warps).
//       Warp w computes gates n in [16w,16w+16) via mma.sync.m16n8k16
//       bf16 2-term split (hi/lo, 3 MMA terms: Ah*Bh + Ah*Bl + Al*Bh).
//       Weights pre-split+fragment-packed in SMEM once; h re-packed to
//       fragment order by the pointwise threads each step. Gates exchanged
//       through a [16][260] fp32 SMEM buffer; P0 + bias folded into pointwise.

#define BB 2048
#define TT 256
#define II 88
#define HH 64
#define OO 13

__device__ float4 g_P0[(size_t)TT * BB * HH];   // [T][B][H] gate pre-acts

typedef unsigned long long ull;

// ---------------- fp32 packed helpers (k1 only) ----------------
__device__ __forceinline__ ull pack2(float lo, float hi) {
    ull r; asm("mov.b64 %0, {%1, %2};" : "=l"(r) : "f"(lo), "f"(hi)); return r;
}
__device__ __forceinline__ ull dup2(float v) {
    ull r; asm("mov.b64 %0, {%1, %1};" : "=l"(r) : "f"(v)); return r;
}
__device__ __forceinline__ void unpack2(ull v, float& lo, float& hi) {
    asm("mov.b64 {%0, %1}, %2;" : "=f"(lo), "=f"(hi) : "l"(v));
}
__device__ __forceinline__ void fma2(ull& d, ull a, ull b) {
    asm("fma.rn.f32x2 %0, %1, %2, %0;" : "+l"(d) : "l"(a), "l"(b));
}

// ---------------- activations ----------------
__device__ __forceinline__ float sigf(float x) {
    return __fdividef(1.0f, 1.0f + __expf(-x));
}
__device__ __forceinline__ float tanhf_fast(float x) {
    return __fdividef(2.0f, 1.0f + __expf(-2.0f * x)) - 1.0f;
}

// ---------------- bf16 split ----------------
__device__ __forceinline__ void split_bf16(float v, unsigned short& hi,
                                           unsigned short& lo) {
    __nv_bfloat16 h = __float2bfloat16(v);
    float r = v - __bfloat162float(h);
    __nv_bfloat16 l = __float2bfloat16(r);
    hi = __bfloat16_as_ushort(h);
    lo = __bfloat16_as_ushort(l);
}

// ---------------- mma.sync bf16 ----------------
__device__ __forceinline__ void mma_bf16(float* d, const uint4& a,
                                         unsigned b0, unsigned b1) {
    asm("mma.sync.aligned.m16n8k16.row.col.f32.bf16.bf16.f32 "
        "{%0,%1,%2,%3}, {%4,%5,%6,%7}, {%8,%9}, {%0,%1,%2,%3};"
        : "+f"(d[0]), "+f"(d[1]), "+f"(d[2]), "+f"(d[3])
        : "r"(a.x), "r"(a.y), "r"(a.z), "r"(a.w), "r"(b0), "r"(b1));
}

// =====================================================================
// K1: fp32 input projection (unchanged from round 3).
// =====================================================================
#define K1_W4   (II * 65)
#define K1_SMEM ((K1_W4 + 64) * 16 + II * 66 * 4)

__global__ void __launch_bounds__(512) k1_inproj(
    const float* __restrict__ x, const float* __restrict__ w_ih0,
    const float* __restrict__ b_ih0, const float* __restrict__ b_hh0)
{
    extern __shared__ float4 sm4[];
    float4* w0p = sm4;
    float4* b0p = sm4 + K1_W4;
    float*  xs  = (float*)(sm4 + K1_W4 + 64);
    float*  ws  = (float*)w0p;

    const int tid = threadIdx.x;

    for (int idx = tid; idx < 256 * II; idx += 512) {
        int g = idx / II, k = idx - g * II;
        int h = g & 63, gate = g >> 6;
        ws[(k * 65 + h) * 4 + gate] = w_ih0[idx];
    }
    if (tid < HH) {
        float4 v;
        v.x = b_ih0[tid]       + b_hh0[tid];
        v.y = b_ih0[tid +  64] + b_hh0[tid +  64];
        v.z = b_ih0[tid + 128] + b_hh0[tid + 128];
        v.w = b_ih0[tid + 192] + b_hh0[tid + 192];
        b0p[tid] = v;
    }
    const int bt0 = blockIdx.x * 64;
    for (int idx = tid; idx < 64 * II; idx += 512) {
        int r = idx / II, k = idx - r * II;
        xs[k * 66 + r] = x[(size_t)bt0 * II + idx];
    }
    __syncthreads();

    const int h  = tid & 63;
    const int r0 = (tid >> 6) * 8;

    ull aI[4], aF[4], aG[4], aO[4];
    {
        float4 bv = b0p[h];
        #pragma unroll
        for (int p = 0; p < 4; p++) {
            aI[p] = dup2(bv.x); aF[p] = dup2(bv.y);
            aG[p] = dup2(bv.z); aO[p] = dup2(bv.w);
        }
    }
    #pragma unroll 4
    for (int k = 0; k < II; k++) {
        float4 w = w0p[k * 65 + h];
        ull wi = dup2(w.x), wf = dup2(w.y), wg = dup2(w.z), wo = dup2(w.w);
        const ull* hv = (const ull*)&xs[k * 66 + r0];
        ull v0 = hv[0], v1 = hv[1], v2 = hv[2], v3 = hv[3];
        fma2(aI[0], wi, v0); fma2(aI[1], wi, v1); fma2(aI[2], wi, v2); fma2(aI[3], wi, v3);
        fma2(aF[0], wf, v0); fma2(aF[1], wf, v1); fma2(aF[2], wf, v2); fma2(aF[3], wf, v3);
        fma2(aG[0], wg, v0); fma2(aG[1], wg, v1); fma2(aG[2], wg, v2); fma2(aG[3], wg, v3);
        fma2(aO[0], wo, v0); fma2(aO[1], wo, v1); fma2(aO[2], wo, v2); fma2(aO[3], wo, v3);
    }
    #pragma unroll
    for (int p = 0; p < 4; p++) {
        float i0, i1, f0, f1, g0, g1, o0, o1;
        unpack2(aI[p], i0, i1); unpack2(aF[p], f0, f1);
        unpack2(aG[p], g0, g1); unpack2(aO[p], o0, o1);
        int bt = bt0 + r0 + 2 * p;
        int t = bt & (TT - 1), b = bt >> 8;
        g_P0[((size_t)t * BB + b) * HH + h] = make_float4(i0, f0, g0, o0);
        bt++; t = bt & (TT - 1); b = bt >> 8;
        g_P0[((size_t)t * BB + b) * HH + h] = make_float4(i1, f1, g1, o1);
    }
}

// =====================================================================
// K2: tensor-core recurrence + FC. 128 CTAs x 512 threads.
// SMEM map (bytes):
//   [0,      65536)  W0 frags: [hi|lo 32K each][nt 32][kt 4][256B tile]
//   [65536, 196608)  W1 frags: [hi|lo 64K each][nt 32][kt 8][256B tile]
//   [196608,200704)  h0 frags: [hi|lo 2K each][kt 4][lane 32][16B]
//   [200704,204800)  h1 frags: same
//   [204800,221440)  gates fp32 [16][260]
// =====================================================================
#define K2_W0   0
#define K2_W1   65536
#define K2_H0   196608
#define K2_H1   200704
#define K2_GT   204800
#define K2_SMEM 221440

__global__ void __launch_bounds__(512) k2_rnn(
    const float* __restrict__ w_hh0, const float* __restrict__ w_ih1,
    const float* __restrict__ w_hh1, const float* __restrict__ b_ih1,
    const float* __restrict__ b_hh1, const float* __restrict__ fc_w,
    const float* __restrict__ fc_b, float* __restrict__ out)
{
    extern __shared__ char smem[];
    char*  W0F = smem + K2_W0;
    char*  W1F = smem + K2_W1;
    char*  H0F = smem + K2_H0;
    char*  H1F = smem + K2_H1;
    float* gts = (float*)(smem + K2_GT);

    const int tid  = threadIdx.x;
    const int lane = tid & 31;
    const int wid  = tid >> 5;

    // ---- init: split weights to bf16 hi/lo, packed in fragment order ----
    // frag addr for element (n, k): nt=n>>3, kt=k>>4, L=((n&7)<<2)+((k&7)>>1),
    //                               reg=(k&8)>>3, half=k&1
    for (int idx = tid; idx < 256 * 64; idx += 512) {   // W0 = w_hh0 [256][64]
        int n = idx >> 6, k = idx & 63;
        float w = w_hh0[idx];
        unsigned short hi, lo; split_bf16(w, hi, lo);
        int off = ((n >> 3) << 10) + ((k >> 4) << 8)
                + ((((n & 7) << 2) + ((k & 7) >> 1)) << 3)
                + (((k & 8) >> 3) << 2) + ((k & 1) << 1);
        *(unsigned short*)(W0F + off)         = hi;
        *(unsigned short*)(W0F + 32768 + off) = lo;
    }
    for (int idx = tid; idx < 256 * 128; idx += 512) {  // W1 = [w_ih1 | w_hh1]
        int n = idx >> 7, k = idx & 127;
        float w = (k < 64) ? w_ih1[n * 64 + k] : w_hh1[n * 64 + (k - 64)];
        unsigned short hi, lo; split_bf16(w, hi, lo);
        int off = ((n >> 3) << 11) + ((k >> 4) << 8)
                + ((((n & 7) << 2) + ((k & 7) >> 1)) << 3)
                + (((k & 8) >> 3) << 2) + ((k & 1) << 1);
        *(unsigned short*)(W1F + off)         = hi;
        *(unsigned short*)(W1F + 65536 + off) = lo;
    }
    for (int idx = tid; idx < 2048; idx += 512)   // zero h frags (8KB)
        ((uint32_t*)H0F)[idx] = 0u;
    __syncthreads();

    // ---- roles ----
    const int n0   = wid * 16;              // mma: this warp's gate base
    const int h    = tid & 63;              // pointwise: h index
    const int rg   = tid >> 6;              // pointwise: rows rg, rg+8
    const int bR0  = blockIdx.x * 16;

    // pointwise-thread constants
    float4 bv;                              // layer-1 bias for this h
    bv.x = b_ih1[h]       + b_hh1[h];
    bv.y = b_ih1[h +  64] + b_hh1[h +  64];
    bv.z = b_ih1[h + 128] + b_hh1[h + 128];
    bv.w = b_ih1[h + 192] + b_hh1[h + 192];
    // h-frag write offsets for rows rg (reg bit0=0) and rg+8 (bit0=1)
    const int fo0 = ((h >> 4) << 9) + ((((rg & 7) << 2) + ((h & 7) >> 1)) << 4)
                  + ((((h & 8) >> 3) << 1) << 2) + ((h & 1) << 1);
    const int fo1 = fo0 + 4;
    // gate-buffer read bases
    const int gr0 = rg * 260 + h, gr1 = (rg + 8) * 260 + h;

    // mma-thread constants
    const int aoff  = lane * 16;            // A-frag lane offset
    const int b0lo  = ((wid * 2) << 10) + lane * 8;       // W0 nt even
    const int b0hi  = (((wid * 2) | 1) << 10) + lane * 8;
    const int b1lo  = ((wid * 2) << 11) + lane * 8;       // W1 nt even
    const int b1hi  = (((wid * 2) | 1) << 11) + lane * 8;
    float* gw0 = &gts[(lane >> 2) * 260 + n0 + (lane & 3) * 2];      // rows 0-7
    float* gw1 = &gts[((lane >> 2) + 8) * 260 + n0 + (lane & 3) * 2];

    float c0a = 0.f, c0b = 0.f, c1a = 0.f, c1b = 0.f;
    float4 xg0 = g_P0[(size_t)(bR0 + rg)     * HH + h];   // t = 0
    float4 xg1 = g_P0[(size_t)(bR0 + rg + 8) * HH + h];

    for (int t = 0; t < TT; t++) {
        // ================= MMA layer 0 =================
        {
            float a0[4] = {0.f, 0.f, 0.f, 0.f};
            float a1[4] = {0.f, 0.f, 0.f, 0.f};
            #pragma unroll
            for (int kt = 0; kt < 4; kt++) {
                uint4 Ah = *(const uint4*)(H0F + kt * 512 + aoff);
                uint4 Al = *(const uint4*)(H0F + 2048 + kt * 512 + aoff);
                uint2 Bh0 = *(const uint2*)(W0F + b0lo + kt * 256);
                uint2 Bl0 = *(const uint2*)(W0F + 32768 + b0lo + kt * 256);
                uint2 Bh1 = *(const uint2*)(W0F + b0hi + kt * 256);
                uint2 Bl1 = *(const uint2*)(W0F + 32768 + b0hi + kt * 256);
                mma_bf16(a0, Ah, Bh0.x, Bh0.y);
                mma_bf16(a0, Ah, Bl0.x, Bl0.y);
                mma_bf16(a0, Al, Bh0.x, Bh0.y);
                mma_bf16(a1, Ah, Bh1.x, Bh1.y);
                mma_bf16(a1, Ah, Bl1.x, Bl1.y);
                mma_bf16(a1, Al, Bh1.x, Bh1.y);
            }
            *(float2*)gw0       = make_float2(a0[0], a0[1]);
            *(float2*)gw1       = make_float2(a0[2], a0[3]);
            *(float2*)(gw0 + 8) = make_float2(a1[0], a1[1]);
            *(float2*)(gw1 + 8) = make_float2(a1[2], a1[3]);
        }
        __syncthreads();

        // ================= pointwise layer 0 =================
        {
            float pi0 = xg0.x + gts[gr0],       pi1 = xg1.x + gts[gr1];
            float pf0 = xg0.y + gts[gr0 + 64],  pf1 = xg1.y + gts[gr1 + 64];
            float pg0 = xg0.z + gts[gr0 + 128], pg1 = xg1.z + gts[gr1 + 128];
            float po0 = xg0.w + gts[gr0 + 192], po1 = xg1.w + gts[gr1 + 192];
            c0a = sigf(pf0) * c0a + sigf(pi0) * tanhf_fast(pg0);
            c0b = sigf(pf1) * c0b + sigf(pi1) * tanhf_fast(pg1);
            float h0v0 = sigf(po0) * tanhf_fast(c0a);
            float h0v1 = sigf(po1) * tanhf_fast(c0b);
            unsigned short hi, lo;
            split_bf16(h0v0, hi, lo);
            *(unsigned short*)(H0F + fo0) = hi;
            *(unsigned short*)(H0F + 2048 + fo0) = lo;
            split_bf16(h0v1, hi, lo);
            *(unsigned short*)(H0F + fo1) = hi;
            *(unsigned short*)(H0F + 2048 + fo1) = lo;
            // prefetch P0 for t+1
            int tn = (t + 1 < TT) ? (t + 1) : t;
            xg0 = g_P0[((size_t)tn * BB + bR0 + rg)     * HH + h];
            xg1 = g_P0[((size_t)tn * BB + bR0 + rg + 8) * HH + h];
        }
        __syncthreads();

        // ================= MMA layer 1 =================
        {
            float a0[4] = {0.f, 0.f, 0.f, 0.f};
            float a1[4] = {0.f, 0.f, 0.f, 0.f};
            #pragma unroll
            for (int kt = 0; kt < 8; kt++) {
                const char* Abase = (kt < 4) ? (H0F + kt * 512)
                                             : (H1F + (kt - 4) * 512);
                uint4 Ah = *(const uint4*)(Abase + aoff);
                uint4 Al = *(const uint4*)(Abase + 2048 + aoff);
                uint2 Bh0 = *(const uint2*)(W1F + b1lo + kt * 256);
                uint2 Bl0 = *(const uint2*)(W1F + 65536 + b1lo + kt * 256);
                uint2 Bh1 = *(const uint2*)(W1F + b1hi + kt * 256);
                uint2 Bl1 = *(const uint2*)(W1F + 65536 + b1hi + kt * 256);
                mma_bf16(a0, Ah, Bh0.x, Bh0.y);
                mma_bf16(a0, Ah, Bl0.x, Bl0.y);
                mma_bf16(a0, Al, Bh0.x, Bh0.y);
                mma_bf16(a1, Ah, Bh1.x, Bh1.y);
                mma_bf16(a1, Ah, Bl1.x, Bl1.y);
                mma_bf16(a1, Al, Bh1.x, Bh1.y);
            }
            *(float2*)gw0       = make_float2(a0[0], a0[1]);
            *(float2*)gw1       = make_float2(a0[2], a0[3]);
            *(float2*)(gw0 + 8) = make_float2(a1[0], a1[1]);
            *(float2*)(gw1 + 8) = make_float2(a1[2], a1[3]);
        }
        __syncthreads();

        // ================= pointwise layer 1 =================
        {
            float pi0 = bv.x + gts[gr0],       pi1 = bv.x + gts[gr1];
            float pf0 = bv.y + gts[gr0 + 64],  pf1 = bv.y + gts[gr1 + 64];
            float pg0 = bv.z + gts[gr0 + 128], pg1 = bv.z + gts[gr1 + 128];
            float po0 = bv.w + gts[gr0 + 192], po1 = bv.w + gts[gr1 + 192];
            c1a = sigf(pf0) * c1a + sigf(pi0) * tanhf_fast(pg0);
            c1b = sigf(pf1) * c1b + sigf(pi1) * tanhf_fast(pg1);
            float h1v0 = sigf(po0) * tanhf_fast(c1a);
            float h1v1 = sigf(po1) * tanhf_fast(c1b);
            unsigned short hi, lo;
            split_bf16(h1v0, hi, lo);
            *(unsigned short*)(H1F + fo0) = hi;
            *(unsigned short*)(H1F + 2048 + fo0) = lo;
            split_bf16(h1v1, hi, lo);
            *(unsigned short*)(H1F + fo1) = hi;
            *(unsigned short*)(H1F + 2048 + fo1) = lo;
            if (t == TT - 1) {   // stash fp32 h1 for FC (own slot, own reader)
                gts[gr0] = h1v0;
                gts[gr1] = h1v1;
            }
        }
        __syncthreads();
    }

    // ---- FC head: out[b][o] = h1 . fc_w[o] + fc_b[o] ----
    for (int idx = tid; idx < 16 * OO; idx += 512) {
        int o = idx / 16, r = idx & 15;
        float s = fc_b[o];
        #pragma unroll 8
        for (int k = 0; k < HH; k++)
            s += fc_w[o * HH + k] * gts[r * 260 + k];
        out[(size_t)(bR0 + r) * OO + o] = s;
    }
}

// =====================================================================
extern "C" void kernel_launch(void* const* d_in, const int* in_sizes, int n_in,
                              void* d_out, int out_size)
{
    (void)in_sizes; (void)n_in; (void)out_size;
    const float* x     = (const float*)d_in[0];
    const float* w_ih0 = (const float*)d_in[1];
    const float* w_hh0 = (const float*)d_in[2];
    const float* b_ih0 = (const float*)d_in[3];
    const float* b_hh0 = (const float*)d_in[4];
    const float* w_ih1 = (const float*)d_in[5];
    const float* w_hh1 = (const float*)d_in[6];
    const float* b_ih1 = (const float*)d_in[7];
    const float* b_hh1 = (const float*)d_in[8];
    const float* fc_w  = (const float*)d_in[9];
    const float* fc_b  = (const float*)d_in[10];
    float* out = (float*)d_out;

    cudaFuncSetAttribute(k1_inproj, cudaFuncAttributeMaxDynamicSharedMemorySize, K1_SMEM);
    cudaFuncSetAttribute(k2_rnn,    cudaFuncAttributeMaxDynamicSharedMemorySize, K2_SMEM);

    k1_inproj<<<(BB * TT) / 64, 512, K1_SMEM>>>(x, w_ih0, b_ih0, b_hh0);
    k2_rnn<<<BB / 16, 512, K2_SMEM>>>(w_hh0, w_ih1, w_hh1, b_ih1, b_hh1,
                                      fc_w, fc_b, out);
}

// round 6
// speedup vs baseline: 2.1035x; 1.3958x over previous
#include <cuda_runtime.h>
#include <cuda_bf16.h>
#include <cstdint>

// MusicRNN: 2-layer LSTM (B=2048, T=256, I=88, H=64) + FC(64->13)
//   K1: tensor-core GEMM  P0[bt][n] = x @ W_ih0^T + b0  (bf16 hi/lo split,
//       3-term mma.m16n8k16). 1024 CTAs x 4 tiles of 128 rows.
//   K2: tensor-core recurrence (proven round-5 structure). 128 CTAs x 512 thr.
//       P0 now read as 4 scalar floats per row (row-major [bt][256]).

#define BB 2048
#define TT 256
#define II 88
#define HH 64
#define OO 13

// P0 scratch: [b*T+t][256] fp32 = 512 MB
__device__ float g_P0[(size_t)TT * BB * 256];

// ---------------- activations ----------------
__device__ __forceinline__ float sigf(float x) {
    return __fdividef(1.0f, 1.0f + __expf(-x));
}
__device__ __forceinline__ float tanhf_fast(float x) {
    return __fdividef(2.0f, 1.0f + __expf(-2.0f * x)) - 1.0f;
}

// ---------------- bf16 split ----------------
__device__ __forceinline__ void split_bf16(float v, unsigned short& hi,
                                           unsigned short& lo) {
    __nv_bfloat16 h = __float2bfloat16(v);
    float r = v - __bfloat162float(h);
    __nv_bfloat16 l = __float2bfloat16(r);
    hi = __bfloat16_as_ushort(h);
    lo = __bfloat16_as_ushort(l);
}

// ---------------- mma.sync bf16 ----------------
__device__ __forceinline__ void mma_bf16(float* d, const uint4& a,
                                         unsigned b0, unsigned b1) {
    asm("mma.sync.aligned.m16n8k16.row.col.f32.bf16.bf16.f32 "
        "{%0,%1,%2,%3}, {%4,%5,%6,%7}, {%8,%9}, {%0,%1,%2,%3};"
        : "+f"(d[0]), "+f"(d[1]), "+f"(d[2]), "+f"(d[3])
        : "r"(a.x), "r"(a.y), "r"(a.z), "r"(a.w), "r"(b0), "r"(b1));
}

// =====================================================================
// K1: tensor GEMM. SMEM: WF [hi|lo][nt32][kt6][256B] = 96KB,
//                        XF [hi|lo][mb8][kt6][512B]  = 48KB, b0s 1KB.
// =====================================================================
#define K1T_WF    0
#define K1T_XF    98304
#define K1T_B0    147456
#define K1T_SMEM  148480
#define K1T_TILES 4

__global__ void __launch_bounds__(512) k1_gemm(
    const float* __restrict__ x, const float* __restrict__ w_ih0,
    const float* __restrict__ b_ih0, const float* __restrict__ b_hh0)
{
    extern __shared__ char smem[];
    char*  WF  = smem + K1T_WF;
    char*  XF  = smem + K1T_XF;
    float* b0s = (float*)(smem + K1T_B0);

    const int tid = threadIdx.x, lane = tid & 31, wid = tid >> 5;

    // one-time: split W_ih0 [256][88] -> frags, zero-pad k 88..95
    for (int j = tid; j < 256 * 96; j += 512) {
        int n = j / 96, k = j - n * 96;
        float w = (k < II) ? w_ih0[n * II + k] : 0.0f;
        unsigned short hi, lo; split_bf16(w, hi, lo);
        int off = (n >> 3) * 1536 + (k >> 4) * 256
                + ((((n & 7) << 2) + ((k & 7) >> 1)) << 3)
                + (((k & 8) >> 3) << 2) + ((k & 1) << 1);
        *(unsigned short*)(WF + off)         = hi;
        *(unsigned short*)(WF + 49152 + off) = lo;
    }
    if (tid < 256) b0s[tid] = b_ih0[tid] + b_hh0[tid];

    const int mb = wid >> 1;            // m-block (16 rows)
    const int nh = wid & 1;             // n half (128 gates)
    const int r  = lane >> 2;
    const int cn = nh * 128 + (lane & 3) * 2;

    for (int tile = 0; tile < K1T_TILES; tile++) {
        const int bt0 = (blockIdx.x * K1T_TILES + tile) * 128;
        __syncthreads();                // XF reuse safe; also covers W split
        // load + split X tile [128][96]
        for (int j = tid; j < 128 * 96; j += 512) {
            int rr = j / 96, k = j - rr * 96;
            float v = (k < II) ? x[(size_t)(bt0 + rr) * II + k] : 0.0f;
            unsigned short hi, lo; split_bf16(v, hi, lo);
            int off = (rr >> 4) * 3072 + (k >> 4) * 512
                    + ((((rr & 7) << 2) + ((k & 7) >> 1)) << 4)
                    + (((k & 8) >> 3) << 3) + (((rr & 8) >> 3) << 2)
                    + ((k & 1) << 1);
            *(unsigned short*)(XF + off)         = hi;
            *(unsigned short*)(XF + 24576 + off) = lo;
        }
        __syncthreads();

        float acc[16][4];
        #pragma unroll
        for (int nt = 0; nt < 16; nt++)
            acc[nt][0] = acc[nt][1] = acc[nt][2] = acc[nt][3] = 0.f;

        #pragma unroll
        for (int kt = 0; kt < 6; kt++) {
            uint4 Ah = *(const uint4*)(XF + mb * 3072 + kt * 512 + lane * 16);
            uint4 Al = *(const uint4*)(XF + 24576 + mb * 3072 + kt * 512 + lane * 16);
            #pragma unroll
            for (int nt = 0; nt < 16; nt++) {
                int ntg = nh * 16 + nt;
                uint2 Bh = *(const uint2*)(WF + ntg * 1536 + kt * 256 + lane * 8);
                uint2 Bl = *(const uint2*)(WF + 49152 + ntg * 1536 + kt * 256 + lane * 8);
                mma_bf16(acc[nt], Ah, Bh.x, Bh.y);
                mma_bf16(acc[nt], Ah, Bl.x, Bl.y);
                mma_bf16(acc[nt], Al, Bh.x, Bh.y);
            }
        }
        // epilogue: + bias, store to P0
        size_t row0 = (size_t)(bt0 + mb * 16 + r) * 256;
        size_t row1 = row0 + 8 * 256;
        #pragma unroll
        for (int nt = 0; nt < 16; nt++) {
            int n = cn + nt * 8;
            float ba = b0s[n], bb = b0s[n + 1];
            *(float2*)&g_P0[row0 + n] = make_float2(acc[nt][0] + ba, acc[nt][1] + bb);
            *(float2*)&g_P0[row1 + n] = make_float2(acc[nt][2] + ba, acc[nt][3] + bb);
        }
    }
}

// =====================================================================
// K2: tensor-core recurrence + FC. 128 CTAs x 512 threads.
// SMEM map (bytes):
//   [0,      65536)  W0 frags: [hi|lo 32K each][nt 32][kt 4][256B tile]
//   [65536, 196608)  W1 frags: [hi|lo 64K each][nt 32][kt 8][256B tile]
//   [196608,200704)  h0 frags: [hi|lo 2K each][kt 4][lane 32][16B]
//   [200704,204800)  h1 frags: same
//   [204800,221440)  gates fp32 [16][260]
// =====================================================================
#define K2_W0   0
#define K2_W1   65536
#define K2_H0   196608
#define K2_H1   200704
#define K2_GT   204800
#define K2_SMEM 221440

__global__ void __launch_bounds__(512) k2_rnn(
    const float* __restrict__ w_hh0, const float* __restrict__ w_ih1,
    const float* __restrict__ w_hh1, const float* __restrict__ b_ih1,
    const float* __restrict__ b_hh1, const float* __restrict__ fc_w,
    const float* __restrict__ fc_b, float* __restrict__ out)
{
    extern __shared__ char smem[];
    char*  W0F = smem + K2_W0;
    char*  W1F = smem + K2_W1;
    char*  H0F = smem + K2_H0;
    char*  H1F = smem + K2_H1;
    float* gts = (float*)(smem + K2_GT);

    const int tid  = threadIdx.x;
    const int lane = tid & 31;
    const int wid  = tid >> 5;

    // ---- init: split weights to bf16 hi/lo, packed in fragment order ----
    for (int idx = tid; idx < 256 * 64; idx += 512) {   // W0 = w_hh0 [256][64]
        int n = idx >> 6, k = idx & 63;
        float w = w_hh0[idx];
        unsigned short hi, lo; split_bf16(w, hi, lo);
        int off = ((n >> 3) << 10) + ((k >> 4) << 8)
                + ((((n & 7) << 2) + ((k & 7) >> 1)) << 3)
                + (((k & 8) >> 3) << 2) + ((k & 1) << 1);
        *(unsigned short*)(W0F + off)         = hi;
        *(unsigned short*)(W0F + 32768 + off) = lo;
    }
    for (int idx = tid; idx < 256 * 128; idx += 512) {  // W1 = [w_ih1 | w_hh1]
        int n = idx >> 7, k = idx & 127;
        float w = (k < 64) ? w_ih1[n * 64 + k] : w_hh1[n * 64 + (k - 64)];
        unsigned short hi, lo; split_bf16(w, hi, lo);
        int off = ((n >> 3) << 11) + ((k >> 4) << 8)
                + ((((n & 7) << 2) + ((k & 7) >> 1)) << 3)
                + (((k & 8) >> 3) << 2) + ((k & 1) << 1);
        *(unsigned short*)(W1F + off)         = hi;
        *(unsigned short*)(W1F + 65536 + off) = lo;
    }
    for (int idx = tid; idx < 2048; idx += 512)   // zero h frags (8KB)
        ((uint32_t*)H0F)[idx] = 0u;
    __syncthreads();

    // ---- roles ----
    const int n0   = wid * 16;              // mma: this warp's gate base
    const int h    = tid & 63;              // pointwise: h index
    const int rg   = tid >> 6;              // pointwise: rows rg, rg+8
    const int bR0  = blockIdx.x * 16;

    // pointwise-thread constants
    float4 bv;                              // layer-1 bias for this h
    bv.x = b_ih1[h]       + b_hh1[h];
    bv.y = b_ih1[h +  64] + b_hh1[h +  64];
    bv.z = b_ih1[h + 128] + b_hh1[h + 128];
    bv.w = b_ih1[h + 192] + b_hh1[h + 192];
    const int fo0 = ((h >> 4) << 9) + ((((rg & 7) << 2) + ((h & 7) >> 1)) << 4)
                  + ((((h & 8) >> 3) << 1) << 2) + ((h & 1) << 1);
    const int fo1 = fo0 + 4;
    const int gr0 = rg * 260 + h, gr1 = (rg + 8) * 260 + h;

    // mma-thread constants
    const int aoff  = lane * 16;
    const int b0lo  = ((wid * 2) << 10) + lane * 8;
    const int b0hi  = (((wid * 2) | 1) << 10) + lane * 8;
    const int b1lo  = ((wid * 2) << 11) + lane * 8;
    const int b1hi  = (((wid * 2) | 1) << 11) + lane * 8;
    float* gw0 = &gts[(lane >> 2) * 260 + n0 + (lane & 3) * 2];
    float* gw1 = &gts[((lane >> 2) + 8) * 260 + n0 + (lane & 3) * 2];

    float c0a = 0.f, c0b = 0.f, c1a = 0.f, c1b = 0.f;

    // P0 row-major [b*T+t][256]; per-thread row streams
    const float* xp0 = g_P0 + (size_t)(bR0 + rg)     * TT * 256 + h;
    const float* xp1 = g_P0 + (size_t)(bR0 + rg + 8) * TT * 256 + h;
    float xa[4], xb[4];
    #pragma unroll
    for (int g = 0; g < 4; g++) { xa[g] = xp0[g * 64]; xb[g] = xp1[g * 64]; }

    for (int t = 0; t < TT; t++) {
        // ================= MMA layer 0 =================
        {
            float a0[4] = {0.f, 0.f, 0.f, 0.f};
            float a1[4] = {0.f, 0.f, 0.f, 0.f};
            #pragma unroll
            for (int kt = 0; kt < 4; kt++) {
                uint4 Ah = *(const uint4*)(H0F + kt * 512 + aoff);
                uint4 Al = *(const uint4*)(H0F + 2048 + kt * 512 + aoff);
                uint2 Bh0 = *(const uint2*)(W0F + b0lo + kt * 256);
                uint2 Bl0 = *(const uint2*)(W0F + 32768 + b0lo + kt * 256);
                uint2 Bh1 = *(const uint2*)(W0F + b0hi + kt * 256);
                uint2 Bl1 = *(const uint2*)(W0F + 32768 + b0hi + kt * 256);
                mma_bf16(a0, Ah, Bh0.x, Bh0.y);
                mma_bf16(a0, Ah, Bl0.x, Bl0.y);
                mma_bf16(a0, Al, Bh0.x, Bh0.y);
                mma_bf16(a1, Ah, Bh1.x, Bh1.y);
                mma_bf16(a1, Ah, Bl1.x, Bl1.y);
                mma_bf16(a1, Al, Bh1.x, Bh1.y);
            }
            *(float2*)gw0       = make_float2(a0[0], a0[1]);
            *(float2*)gw1       = make_float2(a0[2], a0[3]);
            *(float2*)(gw0 + 8) = make_float2(a1[0], a1[1]);
            *(float2*)(gw1 + 8) = make_float2(a1[2], a1[3]);
        }
        __syncthreads();

        // ================= pointwise layer 0 =================
        {
            float pi0 = xa[0] + gts[gr0],       pi1 = xb[0] + gts[gr1];
            float pf0 = xa[1] + gts[gr0 + 64],  pf1 = xb[1] + gts[gr1 + 64];
            float pg0 = xa[2] + gts[gr0 + 128], pg1 = xb[2] + gts[gr1 + 128];
            float po0 = xa[3] + gts[gr0 + 192], po1 = xb[3] + gts[gr1 + 192];
            c0a = sigf(pf0) * c0a + sigf(pi0) * tanhf_fast(pg0);
            c0b = sigf(pf1) * c0b + sigf(pi1) * tanhf_fast(pg1);
            float h0v0 = sigf(po0) * tanhf_fast(c0a);
            float h0v1 = sigf(po1) * tanhf_fast(c0b);
            unsigned short hi, lo;
            split_bf16(h0v0, hi, lo);
            *(unsigned short*)(H0F + fo0) = hi;
            *(unsigned short*)(H0F + 2048 + fo0) = lo;
            split_bf16(h0v1, hi, lo);
            *(unsigned short*)(H0F + fo1) = hi;
            *(unsigned short*)(H0F + 2048 + fo1) = lo;
            // prefetch P0 for t+1
            int tn = (t + 1 < TT) ? (t + 1) : t;
            const float* q0 = xp0 + (size_t)tn * 256;
            const float* q1 = xp1 + (size_t)tn * 256;
            #pragma unroll
            for (int g = 0; g < 4; g++) { xa[g] = q0[g * 64]; xb[g] = q1[g * 64]; }
        }
        __syncthreads();

        // ================= MMA layer 1 =================
        {
            float a0[4] = {0.f, 0.f, 0.f, 0.f};
            float a1[4] = {0.f, 0.f, 0.f, 0.f};
            #pragma unroll
            for (int kt = 0; kt < 8; kt++) {
                const char* Abase = (kt < 4) ? (H0F + kt * 512)
                                             : (H1F + (kt - 4) * 512);
                uint4 Ah = *(const uint4*)(Abase + aoff);
                uint4 Al = *(const uint4*)(Abase + 2048 + aoff);
                uint2 Bh0 = *(const uint2*)(W1F + b1lo + kt * 256);
                uint2 Bl0 = *(const uint2*)(W1F + 65536 + b1lo + kt * 256);
                uint2 Bh1 = *(const uint2*)(W1F + b1hi + kt * 256);
                uint2 Bl1 = *(const uint2*)(W1F + 65536 + b1hi + kt * 256);
                mma_bf16(a0, Ah, Bh0.x, Bh0.y);
                mma_bf16(a0, Ah, Bl0.x, Bl0.y);
                mma_bf16(a0, Al, Bh0.x, Bh0.y);
                mma_bf16(a1, Ah, Bh1.x, Bh1.y);
                mma_bf16(a1, Ah, Bl1.x, Bl1.y);
                mma_bf16(a1, Al, Bh1.x, Bh1.y);
            }
            *(float2*)gw0       = make_float2(a0[0], a0[1]);
            *(float2*)gw1       = make_float2(a0[2], a0[3]);
            *(float2*)(gw0 + 8) = make_float2(a1[0], a1[1]);
            *(float2*)(gw1 + 8) = make_float2(a1[2], a1[3]);
        }
        __syncthreads();

        // ================= pointwise layer 1 =================
        {
            float pi0 = bv.x + gts[gr0],       pi1 = bv.x + gts[gr1];
            float pf0 = bv.y + gts[gr0 + 64],  pf1 = bv.y + gts[gr1 + 64];
            float pg0 = bv.z + gts[gr0 + 128], pg1 = bv.z + gts[gr1 + 128];
            float po0 = bv.w + gts[gr0 + 192], po1 = bv.w + gts[gr1 + 192];
            c1a = sigf(pf0) * c1a + sigf(pi0) * tanhf_fast(pg0);
            c1b = sigf(pf1) * c1b + sigf(pi1) * tanhf_fast(pg1);
            float h1v0 = sigf(po0) * tanhf_fast(c1a);
            float h1v1 = sigf(po1) * tanhf_fast(c1b);
            unsigned short hi, lo;
            split_bf16(h1v0, hi, lo);
            *(unsigned short*)(H1F + fo0) = hi;
            *(unsigned short*)(H1F + 2048 + fo0) = lo;
            split_bf16(h1v1, hi, lo);
            *(unsigned short*)(H1F + fo1) = hi;
            *(unsigned short*)(H1F + 2048 + fo1) = lo;
            if (t == TT - 1) {   // stash fp32 h1 for FC
                gts[gr0] = h1v0;
                gts[gr1] = h1v1;
            }
        }
        __syncthreads();
    }

    // ---- FC head: out[b][o] = h1 . fc_w[o] + fc_b[o] ----
    for (int idx = tid; idx < 16 * OO; idx += 512) {
        int o = idx / 16, r = idx & 15;
        float s = fc_b[o];
        #pragma unroll 8
        for (int k = 0; k < HH; k++)
            s += fc_w[o * HH + k] * gts[r * 260 + k];
        out[(size_t)(bR0 + r) * OO + o] = s;
    }
}

// =====================================================================
extern "C" void kernel_launch(void* const* d_in, const int* in_sizes, int n_in,
                              void* d_out, int out_size)
{
    (void)in_sizes; (void)n_in; (void)out_size;
    const float* x     = (const float*)d_in[0];
    const float* w_ih0 = (const float*)d_in[1];
    const float* w_hh0 = (const float*)d_in[2];
    const float* b_ih0 = (const float*)d_in[3];
    const float* b_hh0 = (const float*)d_in[4];
    const float* w_ih1 = (const float*)d_in[5];
    const float* w_hh1 = (const float*)d_in[6];
    const float* b_ih1 = (const float*)d_in[7];
    const float* b_hh1 = (const float*)d_in[8];
    const float* fc_w  = (const float*)d_in[9];
    const float* fc_b  = (const float*)d_in[10];
    float* out = (float*)d_out;

    cudaFuncSetAttribute(k1_gemm, cudaFuncAttributeMaxDynamicSharedMemorySize, K1T_SMEM);
    cudaFuncSetAttribute(k2_rnn,  cudaFuncAttributeMaxDynamicSharedMemorySize, K2_SMEM);

    k1_gemm<<<(BB * TT) / (128 * K1T_TILES), 512, K1T_SMEM>>>(x, w_ih0, b_ih0, b_hh0);
    k2_rnn<<<BB / 16, 512, K2_SMEM>>>(w_hh0, w_ih1, w_hh1, b_ih1, b_hh1,
                                      fc_w, fc_b, out);
}

// round 8
// speedup vs baseline: 2.3404x; 1.1127x over previous
#include <cuda_runtime.h>
#include <cuda_bf16.h>
#include <cstdint>

// MusicRNN: 2-layer LSTM (B=2048, T=256, I=88, H=64) + FC(64->13)
//   K1: tensor-core GEMM  P0[bt][n] = x @ W_ih0^T + b0  (bf16 hi/lo split).
//   K2: tensor-core recurrence, 2 phases/step (one-step skew on layer 1):
//       MMA phase: G0(t) and G1(t-1) together (shared h0 A-frags);
//       PW  phase: PW1(t-1) then PW0(t). W1-lo cached in registers.

#define BB 2048
#define TT 256
#define II 88
#define HH 64
#define OO 13

// P0 scratch: [b*T+t][256] fp32 = 512 MB
__device__ float g_P0[(size_t)TT * BB * 256];

// ---------------- activations ----------------
__device__ __forceinline__ float sigf(float x) {
    return __fdividef(1.0f, 1.0f + __expf(-x));
}
__device__ __forceinline__ float tanhf_fast(float x) {
    return __fdividef(2.0f, 1.0f + __expf(-2.0f * x)) - 1.0f;
}

// ---------------- bf16 split ----------------
__device__ __forceinline__ void split_bf16(float v, unsigned short& hi,
                                           unsigned short& lo) {
    __nv_bfloat16 h = __float2bfloat16(v);
    float r = v - __bfloat162float(h);
    __nv_bfloat16 l = __float2bfloat16(r);
    hi = __bfloat16_as_ushort(h);
    lo = __bfloat16_as_ushort(l);
}

// ---------------- mma.sync bf16 ----------------
__device__ __forceinline__ void mma_bf16(float* d, const uint4& a,
                                         unsigned b0, unsigned b1) {
    asm("mma.sync.aligned.m16n8k16.row.col.f32.bf16.bf16.f32 "
        "{%0,%1,%2,%3}, {%4,%5,%6,%7}, {%8,%9}, {%0,%1,%2,%3};"
        : "+f"(d[0]), "+f"(d[1]), "+f"(d[2]), "+f"(d[3])
        : "r"(a.x), "r"(a.y), "r"(a.z), "r"(a.w), "r"(b0), "r"(b1));
}

// =====================================================================
// K1: tensor GEMM (unchanged from round 6).
// =====================================================================
#define K1T_WF    0
#define K1T_XF    98304
#define K1T_B0    147456
#define K1T_SMEM  148480
#define K1T_TILES 4

__global__ void __launch_bounds__(512) k1_gemm(
    const float* __restrict__ x, const float* __restrict__ w_ih0,
    const float* __restrict__ b_ih0, const float* __restrict__ b_hh0)
{
    extern __shared__ char smem[];
    char*  WF  = smem + K1T_WF;
    char*  XF  = smem + K1T_XF;
    float* b0s = (float*)(smem + K1T_B0);

    const int tid = threadIdx.x, lane = tid & 31, wid = tid >> 5;

    for (int j = tid; j < 256 * 96; j += 512) {
        int n = j / 96, k = j - n * 96;
        float w = (k < II) ? w_ih0[n * II + k] : 0.0f;
        unsigned short hi, lo; split_bf16(w, hi, lo);
        int off = (n >> 3) * 1536 + (k >> 4) * 256
                + ((((n & 7) << 2) + ((k & 7) >> 1)) << 3)
                + (((k & 8) >> 3) << 2) + ((k & 1) << 1);
        *(unsigned short*)(WF + off)         = hi;
        *(unsigned short*)(WF + 49152 + off) = lo;
    }
    if (tid < 256) b0s[tid] = b_ih0[tid] + b_hh0[tid];

    const int mb = wid >> 1;
    const int nh = wid & 1;
    const int r  = lane >> 2;
    const int cn = nh * 128 + (lane & 3) * 2;

    for (int tile = 0; tile < K1T_TILES; tile++) {
        const int bt0 = (blockIdx.x * K1T_TILES + tile) * 128;
        __syncthreads();
        for (int j = tid; j < 128 * 96; j += 512) {
            int rr = j / 96, k = j - rr * 96;
            float v = (k < II) ? x[(size_t)(bt0 + rr) * II + k] : 0.0f;
            unsigned short hi, lo; split_bf16(v, hi, lo);
            int off = (rr >> 4) * 3072 + (k >> 4) * 512
                    + ((((rr & 7) << 2) + ((k & 7) >> 1)) << 4)
                    + (((k & 8) >> 3) << 3) + (((rr & 8) >> 3) << 2)
                    + ((k & 1) << 1);
            *(unsigned short*)(XF + off)         = hi;
            *(unsigned short*)(XF + 24576 + off) = lo;
        }
        __syncthreads();

        float acc[16][4];
        #pragma unroll
        for (int nt = 0; nt < 16; nt++)
            acc[nt][0] = acc[nt][1] = acc[nt][2] = acc[nt][3] = 0.f;

        #pragma unroll
        for (int kt = 0; kt < 6; kt++) {
            uint4 Ah = *(const uint4*)(XF + mb * 3072 + kt * 512 + lane * 16);
            uint4 Al = *(const uint4*)(XF + 24576 + mb * 3072 + kt * 512 + lane * 16);
            #pragma unroll
            for (int nt = 0; nt < 16; nt++) {
                int ntg = nh * 16 + nt;
                uint2 Bh = *(const uint2*)(WF + ntg * 1536 + kt * 256 + lane * 8);
                uint2 Bl = *(const uint2*)(WF + 49152 + ntg * 1536 + kt * 256 + lane * 8);
                mma_bf16(acc[nt], Ah, Bh.x, Bh.y);
                mma_bf16(acc[nt], Ah, Bl.x, Bl.y);
                mma_bf16(acc[nt], Al, Bh.x, Bh.y);
            }
        }
        size_t row0 = (size_t)(bt0 + mb * 16 + r) * 256;
        size_t row1 = row0 + 8 * 256;
        #pragma unroll
        for (int nt = 0; nt < 16; nt++) {
            int n = cn + nt * 8;
            float ba = b0s[n], bb = b0s[n + 1];
            *(float2*)&g_P0[row0 + n] = make_float2(acc[nt][0] + ba, acc[nt][1] + bb);
            *(float2*)&g_P0[row1 + n] = make_float2(acc[nt][2] + ba, acc[nt][3] + bb);
        }
    }
}

// =====================================================================
// K2: merged-phase tensor recurrence + FC. 128 CTAs x 512 threads.
// SMEM (bytes):
//   [0,     65536)  W0 frags hi|lo: [32K each][nt 32][kt 4][256B]
//   [65536,131072)  W1 frags hi only: [nt 32][kt 8][256B]
//   [131072,135168) h0 frags hi|lo (2K each)
//   [135168,139264) h1 frags hi|lo
//   [139264,155904) gts0 fp32 [16][260]   (G0; also FC h stash)
//   [155904,172544) gts1 fp32 [16][260]   (G1)
//   W1-lo lives in registers (staged through gts area at init).
// =====================================================================
#define K2_W0   0
#define K2_W1H  65536
#define K2_H0   131072
#define K2_H1   135168
#define K2_GT0  139264
#define K2_GT1  155904
#define K2_SMEM 172544

__global__ void __launch_bounds__(512) k2_rnn(
    const float* __restrict__ w_hh0, const float* __restrict__ w_ih1,
    const float* __restrict__ w_hh1, const float* __restrict__ b_ih1,
    const float* __restrict__ b_hh1, const float* __restrict__ fc_w,
    const float* __restrict__ fc_b, float* __restrict__ out)
{
    extern __shared__ char smem[];
    char*  W0F = smem + K2_W0;
    char*  W1H = smem + K2_W1H;
    char*  H0F = smem + K2_H0;
    char*  H1F = smem + K2_H1;
    float* gt0 = (float*)(smem + K2_GT0);
    float* gt1 = (float*)(smem + K2_GT1);
    char*  SCR = smem + K2_GT0;          // 32KB staging scratch (pre-loop only)

    const int tid  = threadIdx.x;
    const int lane = tid & 31;
    const int wid  = tid >> 5;

    // ---- init: W0 hi/lo frags ----
    for (int idx = tid; idx < 256 * 64; idx += 512) {
        int n = idx >> 6, k = idx & 63;
        float w = w_hh0[idx];
        unsigned short hi, lo; split_bf16(w, hi, lo);
        int off = ((n >> 3) << 10) + ((k >> 4) << 8)
                + ((((n & 7) << 2) + ((k & 7) >> 1)) << 3)
                + (((k & 8) >> 3) << 2) + ((k & 1) << 1);
        *(unsigned short*)(W0F + off)         = hi;
        *(unsigned short*)(W0F + 32768 + off) = lo;
    }
    // ---- init: W1 hi frags ----
    for (int idx = tid; idx < 256 * 128; idx += 512) {
        int n = idx >> 7, k = idx & 127;
        float w = (k < 64) ? w_ih1[n * 64 + k] : w_hh1[n * 64 + (k - 64)];
        unsigned short hi, lo; split_bf16(w, hi, lo);
        int off = ((n >> 3) << 11) + ((k >> 4) << 8)
                + ((((n & 7) << 2) + ((k & 7) >> 1)) << 3)
                + (((k & 8) >> 3) << 2) + ((k & 1) << 1);
        *(unsigned short*)(W1H + off) = hi;
    }
    for (int idx = tid; idx < 2048; idx += 512)    // zero H0F+H1F (8KB)
        ((uint32_t*)H0F)[idx] = 0u;

    // ---- stage W1-lo into registers (2 passes through SCR) ----
    uint2 w1lo[16];                      // [kt][nh]  (kt*2 + nh)
    #pragma unroll
    for (int pass = 0; pass < 2; pass++) {
        __syncthreads();
        for (int idx = tid; idx < 256 * 64; idx += 512) {
            int n = idx >> 6, kk = idx & 63;       // kk = k - pass*64
            float w = pass ? w_hh1[n * 64 + kk] : w_ih1[n * 64 + kk];
            unsigned short hi, lo; split_bf16(w, hi, lo);
            int off = ((n >> 3) << 10) + (((kk >> 4) & 3) << 8)
                    + ((((n & 7) << 2) + ((kk & 7) >> 1)) << 3)
                    + (((kk & 8) >> 3) << 2) + ((kk & 1) << 1);
            *(unsigned short*)(SCR + off) = lo;
        }
        __syncthreads();
        #pragma unroll
        for (int j = 0; j < 4; j++) {
            w1lo[(pass * 4 + j) * 2 + 0] =
                *(const uint2*)(SCR + ((wid * 2) << 10) + j * 256 + lane * 8);
            w1lo[(pass * 4 + j) * 2 + 1] =
                *(const uint2*)(SCR + (((wid * 2) | 1) << 10) + j * 256 + lane * 8);
        }
    }
    __syncthreads();   // SCR reads done; gts area free for gate use

    // ---- roles / constants ----
    const int n0  = wid * 16;
    const int h   = tid & 63;
    const int rg  = tid >> 6;
    const int bR0 = blockIdx.x * 16;

    float4 bv;                              // layer-1 bias
    bv.x = b_ih1[h]       + b_hh1[h];
    bv.y = b_ih1[h +  64] + b_hh1[h +  64];
    bv.z = b_ih1[h + 128] + b_hh1[h + 128];
    bv.w = b_ih1[h + 192] + b_hh1[h + 192];
    const int fo0 = ((h >> 4) << 9) + ((((rg & 7) << 2) + ((h & 7) >> 1)) << 4)
                  + ((((h & 8) >> 3) << 1) << 2) + ((h & 1) << 1);
    const int fo1 = fo0 + 4;
    const int gr0 = rg * 260 + h, gr1 = (rg + 8) * 260 + h;

    const int aoff = lane * 16;
    const int b0lo = ((wid * 2) << 10) + lane * 8;
    const int b0hi = (((wid * 2) | 1) << 10) + lane * 8;
    const int b1lo = ((wid * 2) << 11) + lane * 8;
    const int b1hi = (((wid * 2) | 1) << 11) + lane * 8;
    const int gwo0 = (lane >> 2) * 260 + n0 + (lane & 3) * 2;
    const int gwo1 = gwo0 + 8 * 260;

    float c0a = 0.f, c0b = 0.f, c1a = 0.f, c1b = 0.f;

    const float* xp0 = g_P0 + (size_t)(bR0 + rg)     * TT * 256 + h;
    const float* xp1 = g_P0 + (size_t)(bR0 + rg + 8) * TT * 256 + h;
    float xa[4], xb[4];
    #pragma unroll
    for (int g = 0; g < 4; g++) { xa[g] = xp0[g * 64]; xb[g] = xp1[g * 64]; }

    for (int t = 0; t < TT; t++) {
        // ========== MMA phase: G0(t) + G1(t-1) ==========
        {
            float g0a[4] = {0.f,0.f,0.f,0.f}, g0b[4] = {0.f,0.f,0.f,0.f};
            float g1a[4] = {0.f,0.f,0.f,0.f}, g1b[4] = {0.f,0.f,0.f,0.f};
            #pragma unroll
            for (int kt = 0; kt < 4; kt++) {
                uint4 Ah = *(const uint4*)(H0F + kt * 512 + aoff);
                uint4 Al = *(const uint4*)(H0F + 2048 + kt * 512 + aoff);
                uint2 Bh0 = *(const uint2*)(W0F + b0lo + kt * 256);
                uint2 Bl0 = *(const uint2*)(W0F + 32768 + b0lo + kt * 256);
                uint2 Bh1 = *(const uint2*)(W0F + b0hi + kt * 256);
                uint2 Bl1 = *(const uint2*)(W0F + 32768 + b0hi + kt * 256);
                mma_bf16(g0a, Ah, Bh0.x, Bh0.y);
                mma_bf16(g0a, Ah, Bl0.x, Bl0.y);
                mma_bf16(g0a, Al, Bh0.x, Bh0.y);
                mma_bf16(g0b, Ah, Bh1.x, Bh1.y);
                mma_bf16(g0b, Ah, Bl1.x, Bl1.y);
                mma_bf16(g0b, Al, Bh1.x, Bh1.y);
                uint2 Ch0 = *(const uint2*)(W1H + b1lo + kt * 256);
                uint2 Ch1 = *(const uint2*)(W1H + b1hi + kt * 256);
                mma_bf16(g1a, Ah, Ch0.x, Ch0.y);
                mma_bf16(g1a, Ah, w1lo[kt * 2].x, w1lo[kt * 2].y);
                mma_bf16(g1a, Al, Ch0.x, Ch0.y);
                mma_bf16(g1b, Ah, Ch1.x, Ch1.y);
                mma_bf16(g1b, Ah, w1lo[kt * 2 + 1].x, w1lo[kt * 2 + 1].y);
                mma_bf16(g1b, Al, Ch1.x, Ch1.y);
            }
            #pragma unroll
            for (int kt = 4; kt < 8; kt++) {
                uint4 Ah = *(const uint4*)(H1F + (kt - 4) * 512 + aoff);
                uint4 Al = *(const uint4*)(H1F + 2048 + (kt - 4) * 512 + aoff);
                uint2 Ch0 = *(const uint2*)(W1H + b1lo + kt * 256);
                uint2 Ch1 = *(const uint2*)(W1H + b1hi + kt * 256);
                mma_bf16(g1a, Ah, Ch0.x, Ch0.y);
                mma_bf16(g1a, Ah, w1lo[kt * 2].x, w1lo[kt * 2].y);
                mma_bf16(g1a, Al, Ch0.x, Ch0.y);
                mma_bf16(g1b, Ah, Ch1.x, Ch1.y);
                mma_bf16(g1b, Ah, w1lo[kt * 2 + 1].x, w1lo[kt * 2 + 1].y);
                mma_bf16(g1b, Al, Ch1.x, Ch1.y);
            }
            *(float2*)(gt0 + gwo0)     = make_float2(g0a[0], g0a[1]);
            *(float2*)(gt0 + gwo1)     = make_float2(g0a[2], g0a[3]);
            *(float2*)(gt0 + gwo0 + 8) = make_float2(g0b[0], g0b[1]);
            *(float2*)(gt0 + gwo1 + 8) = make_float2(g0b[2], g0b[3]);
            *(float2*)(gt1 + gwo0)     = make_float2(g1a[0], g1a[1]);
            *(float2*)(gt1 + gwo1)     = make_float2(g1a[2], g1a[3]);
            *(float2*)(gt1 + gwo0 + 8) = make_float2(g1b[0], g1b[1]);
            *(float2*)(gt1 + gwo1 + 8) = make_float2(g1b[2], g1b[3]);
        }
        __syncthreads();

        // ========== PW phase: PW1(t-1) then PW0(t) ==========
        if (t > 0) {
            float qi0 = bv.x + gt1[gr0],       qi1 = bv.x + gt1[gr1];
            float qf0 = bv.y + gt1[gr0 + 64],  qf1 = bv.y + gt1[gr1 + 64];
            float qg0 = bv.z + gt1[gr0 + 128], qg1 = bv.z + gt1[gr1 + 128];
            float qo0 = bv.w + gt1[gr0 + 192], qo1 = bv.w + gt1[gr1 + 192];
            c1a = sigf(qf0) * c1a + sigf(qi0) * tanhf_fast(qg0);
            c1b = sigf(qf1) * c1b + sigf(qi1) * tanhf_fast(qg1);
            float h1v0 = sigf(qo0) * tanhf_fast(c1a);
            float h1v1 = sigf(qo1) * tanhf_fast(c1b);
            unsigned short hi, lo;
            split_bf16(h1v0, hi, lo);
            *(unsigned short*)(H1F + fo0) = hi;
            *(unsigned short*)(H1F + 2048 + fo0) = lo;
            split_bf16(h1v1, hi, lo);
            *(unsigned short*)(H1F + fo1) = hi;
            *(unsigned short*)(H1F + 2048 + fo1) = lo;
        }
        {
            float pi0 = xa[0] + gt0[gr0],       pi1 = xb[0] + gt0[gr1];
            float pf0 = xa[1] + gt0[gr0 + 64],  pf1 = xb[1] + gt0[gr1 + 64];
            float pg0 = xa[2] + gt0[gr0 + 128], pg1 = xb[2] + gt0[gr1 + 128];
            float po0 = xa[3] + gt0[gr0 + 192], po1 = xb[3] + gt0[gr1 + 192];
            c0a = sigf(pf0) * c0a + sigf(pi0) * tanhf_fast(pg0);
            c0b = sigf(pf1) * c0b + sigf(pi1) * tanhf_fast(pg1);
            float h0v0 = sigf(po0) * tanhf_fast(c0a);
            float h0v1 = sigf(po1) * tanhf_fast(c0b);
            unsigned short hi, lo;
            split_bf16(h0v0, hi, lo);
            *(unsigned short*)(H0F + fo0) = hi;
            *(unsigned short*)(H0F + 2048 + fo0) = lo;
            split_bf16(h0v1, hi, lo);
            *(unsigned short*)(H0F + fo1) = hi;
            *(unsigned short*)(H0F + 2048 + fo1) = lo;
            int tn = (t + 1 < TT) ? (t + 1) : t;
            const float* q0 = xp0 + (size_t)tn * 256;
            const float* q1 = xp1 + (size_t)tn * 256;
            #pragma unroll
            for (int g = 0; g < 4; g++) { xa[g] = q0[g * 64]; xb[g] = q1[g * 64]; }
        }
        __syncthreads();
    }

    // ========== epilogue: G1(TT-1) + PW1(TT-1) ==========
    {
        float g1a[4] = {0.f,0.f,0.f,0.f}, g1b[4] = {0.f,0.f,0.f,0.f};
        #pragma unroll
        for (int kt = 0; kt < 8; kt++) {
            const char* Ab = (kt < 4) ? (H0F + kt * 512) : (H1F + (kt - 4) * 512);
            uint4 Ah = *(const uint4*)(Ab + aoff);
            uint4 Al = *(const uint4*)(Ab + 2048 + aoff);
            uint2 Ch0 = *(const uint2*)(W1H + b1lo + kt * 256);
            uint2 Ch1 = *(const uint2*)(W1H + b1hi + kt * 256);
            mma_bf16(g1a, Ah, Ch0.x, Ch0.y);
            mma_bf16(g1a, Ah, w1lo[kt * 2].x, w1lo[kt * 2].y);
            mma_bf16(g1a, Al, Ch0.x, Ch0.y);
            mma_bf16(g1b, Ah, Ch1.x, Ch1.y);
            mma_bf16(g1b, Ah, w1lo[kt * 2 + 1].x, w1lo[kt * 2 + 1].y);
            mma_bf16(g1b, Al, Ch1.x, Ch1.y);
        }
        *(float2*)(gt1 + gwo0)     = make_float2(g1a[0], g1a[1]);
        *(float2*)(gt1 + gwo1)     = make_float2(g1a[2], g1a[3]);
        *(float2*)(gt1 + gwo0 + 8) = make_float2(g1b[0], g1b[1]);
        *(float2*)(gt1 + gwo1 + 8) = make_float2(g1b[2], g1b[3]);
    }
    __syncthreads();
    {
        float qi0 = bv.x + gt1[gr0],       qi1 = bv.x + gt1[gr1];
        float qf0 = bv.y + gt1[gr0 + 64],  qf1 = bv.y + gt1[gr1 + 64];
        float qg0 = bv.z + gt1[gr0 + 128], qg1 = bv.z + gt1[gr1 + 128];
        float qo0 = bv.w + gt1[gr0 + 192], qo1 = bv.w + gt1[gr1 + 192];
        c1a = sigf(qf0) * c1a + sigf(qi0) * tanhf_fast(qg0);
        c1b = sigf(qf1) * c1b + sigf(qi1) * tanhf_fast(qg1);
        gt0[gr0] = sigf(qo0) * tanhf_fast(c1a);   // final h1 (fp32) for FC
        gt0[gr1] = sigf(qo1) * tanhf_fast(c1b);
    }
    __syncthreads();

    // ---- FC head ----
    for (int idx = tid; idx < 16 * OO; idx += 512) {
        int o = idx / 16, r = idx & 15;
        float s = fc_b[o];
        #pragma unroll 8
        for (int k = 0; k < HH; k++)
            s += fc_w[o * HH + k] * gt0[r * 260 + k];
        out[(size_t)(bR0 + r) * OO + o] = s;
    }
}

// =====================================================================
extern "C" void kernel_launch(void* const* d_in, const int* in_sizes, int n_in,
                              void* d_out, int out_size)
{
    (void)in_sizes; (void)n_in; (void)out_size;
    const float* x     = (const float*)d_in[0];
    const float* w_ih0 = (const float*)d_in[1];
    const float* w_hh0 = (const float*)d_in[2];
    const float* b_ih0 = (const float*)d_in[3];
    const float* b_hh0 = (const float*)d_in[4];
    const float* w_ih1 = (const float*)d_in[5];
    const float* w_hh1 = (const float*)d_in[6];
    const float* b_ih1 = (const float*)d_in[7];
    const float* b_hh1 = (const float*)d_in[8];
    const float* fc_w  = (const float*)d_in[9];
    const float* fc_b  = (const float*)d_in[10];
    float* out = (float*)d_out;

    cudaFuncSetAttribute(k1_gemm, cudaFuncAttributeMaxDynamicSharedMemorySize, K1T_SMEM);
    cudaFuncSetAttribute(k2_rnn,  cudaFuncAttributeMaxDynamicSharedMemorySize, K2_SMEM);

    k1_gemm<<<(BB * TT) / (128 * K1T_TILES), 512, K1T_SMEM>>>(x, w_ih0, b_ih0, b_hh0);
    k2_rnn<<<BB / 16, 512, K2_SMEM>>>(w_hh0, w_ih1, w_hh1, b_ih1, b_hh1,
                                      fc_w, fc_b, out);
}

// round 9
// speedup vs baseline: 2.9353x; 1.2542x over previous
#include <cuda_runtime.h>
#include <cuda_fp16.h>
#include <cstdint>

// MusicRNN: 2-layer LSTM (B=2048, T=256, I=88, H=64) + FC(64->13)
//   fp16 2-term scheme: weights single fp16, activations split hi/lo fp16.
//   Per matvec: 2 mma terms (Ah*B + Al*B) instead of 3 -> 33% fewer HMMA.
//   K1: tensor GEMM, 1024 threads (32 warps), 4 tiles of 128 rows per CTA.
//   K2: merged-phase tensor recurrence (round-8 structure), 512 threads.

#define BB 2048
#define TT 256
#define II 88
#define HH 64
#define OO 13

// P0 scratch: [b*T+t][256] fp32 = 512 MB
__device__ float g_P0[(size_t)TT * BB * 256];

// ---------------- activations ----------------
__device__ __forceinline__ float sigf(float x) {
    return __fdividef(1.0f, 1.0f + __expf(-x));
}
__device__ __forceinline__ float tanhf_fast(float x) {
    return __fdividef(2.0f, 1.0f + __expf(-2.0f * x)) - 1.0f;
}

// ---------------- fp16 split ----------------
__device__ __forceinline__ void split_fp16(float v, unsigned short& hi,
                                           unsigned short& lo) {
    __half h = __float2half_rn(v);
    float r = v - __half2float(h);
    __half l = __float2half_rn(r);
    hi = __half_as_ushort(h);
    lo = __half_as_ushort(l);
}

// ---------------- mma.sync fp16 (f32 accum) ----------------
__device__ __forceinline__ void mma_fp16(float* d, const uint4& a,
                                         unsigned b0, unsigned b1) {
    asm("mma.sync.aligned.m16n8k16.row.col.f32.f16.f16.f32 "
        "{%0,%1,%2,%3}, {%4,%5,%6,%7}, {%8,%9}, {%0,%1,%2,%3};"
        : "+f"(d[0]), "+f"(d[1]), "+f"(d[2]), "+f"(d[3])
        : "r"(a.x), "r"(a.y), "r"(a.z), "r"(a.w), "r"(b0), "r"(b1));
}

// =====================================================================
// K1: tensor GEMM. 1024 threads. SMEM: WF single fp16 48KB,
//     XF hi/lo fp16 48KB, b0s 1KB.
// =====================================================================
#define K1T_WF    0
#define K1T_XF    49152
#define K1T_B0    98304
#define K1T_SMEM  99328
#define K1T_TILES 4

__global__ void __launch_bounds__(1024) k1_gemm(
    const float* __restrict__ x, const float* __restrict__ w_ih0,
    const float* __restrict__ b_ih0, const float* __restrict__ b_hh0)
{
    extern __shared__ char smem[];
    char*  WF  = smem + K1T_WF;
    char*  XF  = smem + K1T_XF;
    float* b0s = (float*)(smem + K1T_B0);

    const int tid = threadIdx.x, lane = tid & 31, wid = tid >> 5;

    // one-time: W_ih0 [256][88] -> single fp16 frags, zero-pad k 88..95
    for (int j = tid; j < 256 * 96; j += 1024) {
        int n = j / 96, k = j - n * 96;
        float w = (k < II) ? w_ih0[n * II + k] : 0.0f;
        int off = (n >> 3) * 1536 + (k >> 4) * 256
                + ((((n & 7) << 2) + ((k & 7) >> 1)) << 3)
                + (((k & 8) >> 3) << 2) + ((k & 1) << 1);
        *(unsigned short*)(WF + off) = __half_as_ushort(__float2half_rn(w));
    }
    if (tid < 256) b0s[tid] = b_ih0[tid] + b_hh0[tid];

    const int mb = wid >> 2;            // m-block (16 rows), 0..7
    const int nq = wid & 3;             // n quarter (64 gates), 0..3
    const int r  = lane >> 2;
    const int cn = nq * 64 + (lane & 3) * 2;

    for (int tile = 0; tile < K1T_TILES; tile++) {
        const int bt0 = (blockIdx.x * K1T_TILES + tile) * 128;
        __syncthreads();                // XF reuse safe; also covers W fill
        // load + split X tile [128][96]
        for (int j = tid; j < 128 * 96; j += 1024) {
            int rr = j / 96, k = j - rr * 96;
            float v = (k < II) ? x[(size_t)(bt0 + rr) * II + k] : 0.0f;
            unsigned short hi, lo; split_fp16(v, hi, lo);
            int off = (rr >> 4) * 3072 + (k >> 4) * 512
                    + ((((rr & 7) << 2) + ((k & 7) >> 1)) << 4)
                    + (((k & 8) >> 3) << 3) + (((rr & 8) >> 3) << 2)
                    + ((k & 1) << 1);
            *(unsigned short*)(XF + off)         = hi;
            *(unsigned short*)(XF + 24576 + off) = lo;
        }
        __syncthreads();

        float acc[8][4];
        #pragma unroll
        for (int nt = 0; nt < 8; nt++)
            acc[nt][0] = acc[nt][1] = acc[nt][2] = acc[nt][3] = 0.f;

        #pragma unroll
        for (int kt = 0; kt < 6; kt++) {
            uint4 Ah = *(const uint4*)(XF + mb * 3072 + kt * 512 + lane * 16);
            uint4 Al = *(const uint4*)(XF + 24576 + mb * 3072 + kt * 512 + lane * 16);
            #pragma unroll
            for (int nt = 0; nt < 8; nt++) {
                int ntg = nq * 8 + nt;
                uint2 B = *(const uint2*)(WF + ntg * 1536 + kt * 256 + lane * 8);
                mma_fp16(acc[nt], Ah, B.x, B.y);
                mma_fp16(acc[nt], Al, B.x, B.y);
            }
        }
        // epilogue: + bias, store to P0
        size_t row0 = (size_t)(bt0 + mb * 16 + r) * 256;
        size_t row1 = row0 + 8 * 256;
        #pragma unroll
        for (int nt = 0; nt < 8; nt++) {
            int n = cn + nt * 8;
            float ba = b0s[n], bb = b0s[n + 1];
            *(float2*)&g_P0[row0 + n] = make_float2(acc[nt][0] + ba, acc[nt][1] + bb);
            *(float2*)&g_P0[row1 + n] = make_float2(acc[nt][2] + ba, acc[nt][3] + bb);
        }
    }
}

// =====================================================================
// K2: merged-phase tensor recurrence + FC. 128 CTAs x 512 threads.
// SMEM (bytes):
//   [0,     32768)  W0 frags fp16: [nt 32][kt 4][256B]
//   [32768, 98304)  W1 frags fp16: [nt 32][kt 8][256B]
//   [98304,102400)  h0 frags hi|lo fp16 (2K each)
//   [102400,106496) h1 frags hi|lo fp16
//   [106496,123136) gt0 fp32 [16][260]   (G0; also FC h stash)
//   [123136,139776) gt1 fp32 [16][260]   (G1)
// =====================================================================
#define K2_W0   0
#define K2_W1   32768
#define K2_H0   98304
#define K2_H1   102400
#define K2_GT0  106496
#define K2_GT1  123136
#define K2_SMEM 139776

__global__ void __launch_bounds__(512) k2_rnn(
    const float* __restrict__ w_hh0, const float* __restrict__ w_ih1,
    const float* __restrict__ w_hh1, const float* __restrict__ b_ih1,
    const float* __restrict__ b_hh1, const float* __restrict__ fc_w,
    const float* __restrict__ fc_b, float* __restrict__ out)
{
    extern __shared__ char smem[];
    char*  W0F = smem + K2_W0;
    char*  W1F = smem + K2_W1;
    char*  H0F = smem + K2_H0;
    char*  H1F = smem + K2_H1;
    float* gt0 = (float*)(smem + K2_GT0);
    float* gt1 = (float*)(smem + K2_GT1);

    const int tid  = threadIdx.x;
    const int lane = tid & 31;
    const int wid  = tid >> 5;

    // ---- init: W0 single-fp16 frags ----
    for (int idx = tid; idx < 256 * 64; idx += 512) {
        int n = idx >> 6, k = idx & 63;
        int off = ((n >> 3) << 10) + ((k >> 4) << 8)
                + ((((n & 7) << 2) + ((k & 7) >> 1)) << 3)
                + (((k & 8) >> 3) << 2) + ((k & 1) << 1);
        *(unsigned short*)(W0F + off) =
            __half_as_ushort(__float2half_rn(w_hh0[idx]));
    }
    // ---- init: W1 single-fp16 frags (k = [w_ih1 | w_hh1]) ----
    for (int idx = tid; idx < 256 * 128; idx += 512) {
        int n = idx >> 7, k = idx & 127;
        float w = (k < 64) ? w_ih1[n * 64 + k] : w_hh1[n * 64 + (k - 64)];
        int off = ((n >> 3) << 11) + ((k >> 4) << 8)
                + ((((n & 7) << 2) + ((k & 7) >> 1)) << 3)
                + (((k & 8) >> 3) << 2) + ((k & 1) << 1);
        *(unsigned short*)(W1F + off) = __half_as_ushort(__float2half_rn(w));
    }
    for (int idx = tid; idx < 2048; idx += 512)    // zero H0F+H1F (8KB)
        ((uint32_t*)H0F)[idx] = 0u;
    __syncthreads();

    // ---- roles / constants ----
    const int n0  = wid * 16;
    const int h   = tid & 63;
    const int rg  = tid >> 6;
    const int bR0 = blockIdx.x * 16;

    float4 bv;                              // layer-1 bias
    bv.x = b_ih1[h]       + b_hh1[h];
    bv.y = b_ih1[h +  64] + b_hh1[h +  64];
    bv.z = b_ih1[h + 128] + b_hh1[h + 128];
    bv.w = b_ih1[h + 192] + b_hh1[h + 192];
    const int fo0 = ((h >> 4) << 9) + ((((rg & 7) << 2) + ((h & 7) >> 1)) << 4)
                  + ((((h & 8) >> 3) << 1) << 2) + ((h & 1) << 1);
    const int fo1 = fo0 + 4;
    const int gr0 = rg * 260 + h, gr1 = (rg + 8) * 260 + h;

    const int aoff = lane * 16;
    const int b0lo = ((wid * 2) << 10) + lane * 8;
    const int b0hi = (((wid * 2) | 1) << 10) + lane * 8;
    const int b1lo = ((wid * 2) << 11) + lane * 8;
    const int b1hi = (((wid * 2) | 1) << 11) + lane * 8;
    const int gwo0 = (lane >> 2) * 260 + n0 + (lane & 3) * 2;
    const int gwo1 = gwo0 + 8 * 260;

    float c0a = 0.f, c0b = 0.f, c1a = 0.f, c1b = 0.f;

    const float* xp0 = g_P0 + (size_t)(bR0 + rg)     * TT * 256 + h;
    const float* xp1 = g_P0 + (size_t)(bR0 + rg + 8) * TT * 256 + h;
    float xa[4], xb[4];
    #pragma unroll
    for (int g = 0; g < 4; g++) { xa[g] = xp0[g * 64]; xb[g] = xp1[g * 64]; }

    for (int t = 0; t < TT; t++) {
        // ========== MMA phase: G0(t) + G1(t-1), 2-term fp16 ==========
        {
            float g0a[4] = {0.f,0.f,0.f,0.f}, g0b[4] = {0.f,0.f,0.f,0.f};
            float g1a[4] = {0.f,0.f,0.f,0.f}, g1b[4] = {0.f,0.f,0.f,0.f};
            #pragma unroll
            for (int kt = 0; kt < 4; kt++) {
                uint4 Ah = *(const uint4*)(H0F + kt * 512 + aoff);
                uint4 Al = *(const uint4*)(H0F + 2048 + kt * 512 + aoff);
                uint2 B0 = *(const uint2*)(W0F + b0lo + kt * 256);
                uint2 B1 = *(const uint2*)(W0F + b0hi + kt * 256);
                mma_fp16(g0a, Ah, B0.x, B0.y);
                mma_fp16(g0a, Al, B0.x, B0.y);
                mma_fp16(g0b, Ah, B1.x, B1.y);
                mma_fp16(g0b, Al, B1.x, B1.y);
                uint2 C0 = *(const uint2*)(W1F + b1lo + kt * 256);
                uint2 C1 = *(const uint2*)(W1F + b1hi + kt * 256);
                mma_fp16(g1a, Ah, C0.x, C0.y);
                mma_fp16(g1a, Al, C0.x, C0.y);
                mma_fp16(g1b, Ah, C1.x, C1.y);
                mma_fp16(g1b, Al, C1.x, C1.y);
            }
            #pragma unroll
            for (int kt = 4; kt < 8; kt++) {
                uint4 Ah = *(const uint4*)(H1F + (kt - 4) * 512 + aoff);
                uint4 Al = *(const uint4*)(H1F + 2048 + (kt - 4) * 512 + aoff);
                uint2 C0 = *(const uint2*)(W1F + b1lo + kt * 256);
                uint2 C1 = *(const uint2*)(W1F + b1hi + kt * 256);
                mma_fp16(g1a, Ah, C0.x, C0.y);
                mma_fp16(g1a, Al, C0.x, C0.y);
                mma_fp16(g1b, Ah, C1.x, C1.y);
                mma_fp16(g1b, Al, C1.x, C1.y);
            }
            *(float2*)(gt0 + gwo0)     = make_float2(g0a[0], g0a[1]);
            *(float2*)(gt0 + gwo1)     = make_float2(g0a[2], g0a[3]);
            *(float2*)(gt0 + gwo0 + 8) = make_float2(g0b[0], g0b[1]);
            *(float2*)(gt0 + gwo1 + 8) = make_float2(g0b[2], g0b[3]);
            *(float2*)(gt1 + gwo0)     = make_float2(g1a[0], g1a[1]);
            *(float2*)(gt1 + gwo1)     = make_float2(g1a[2], g1a[3]);
            *(float2*)(gt1 + gwo0 + 8) = make_float2(g1b[0], g1b[1]);
            *(float2*)(gt1 + gwo1 + 8) = make_float2(g1b[2], g1b[3]);
        }
        __syncthreads();

        // ========== PW phase: PW1(t-1) then PW0(t) ==========
        if (t > 0) {
            float qi0 = bv.x + gt1[gr0],       qi1 = bv.x + gt1[gr1];
            float qf0 = bv.y + gt1[gr0 + 64],  qf1 = bv.y + gt1[gr1 + 64];
            float qg0 = bv.z + gt1[gr0 + 128], qg1 = bv.z + gt1[gr1 + 128];
            float qo0 = bv.w + gt1[gr0 + 192], qo1 = bv.w + gt1[gr1 + 192];
            c1a = sigf(qf0) * c1a + sigf(qi0) * tanhf_fast(qg0);
            c1b = sigf(qf1) * c1b + sigf(qi1) * tanhf_fast(qg1);
            float h1v0 = sigf(qo0) * tanhf_fast(c1a);
            float h1v1 = sigf(qo1) * tanhf_fast(c1b);
            unsigned short hi, lo;
            split_fp16(h1v0, hi, lo);
            *(unsigned short*)(H1F + fo0) = hi;
            *(unsigned short*)(H1F + 2048 + fo0) = lo;
            split_fp16(h1v1, hi, lo);
            *(unsigned short*)(H1F + fo1) = hi;
            *(unsigned short*)(H1F + 2048 + fo1) = lo;
        }
        {
            float pi0 = xa[0] + gt0[gr0],       pi1 = xb[0] + gt0[gr1];
            float pf0 = xa[1] + gt0[gr0 + 64],  pf1 = xb[1] + gt0[gr1 + 64];
            float pg0 = xa[2] + gt0[gr0 + 128], pg1 = xb[2] + gt0[gr1 + 128];
            float po0 = xa[3] + gt0[gr0 + 192], po1 = xb[3] + gt0[gr1 + 192];
            c0a = sigf(pf0) * c0a + sigf(pi0) * tanhf_fast(pg0);
            c0b = sigf(pf1) * c0b + sigf(pi1) * tanhf_fast(pg1);
            float h0v0 = sigf(po0) * tanhf_fast(c0a);
            float h0v1 = sigf(po1) * tanhf_fast(c0b);
            unsigned short hi, lo;
            split_fp16(h0v0, hi, lo);
            *(unsigned short*)(H0F + fo0) = hi;
            *(unsigned short*)(H0F + 2048 + fo0) = lo;
            split_fp16(h0v1, hi, lo);
            *(unsigned short*)(H0F + fo1) = hi;
            *(unsigned short*)(H0F + 2048 + fo1) = lo;
            int tn = (t + 1 < TT) ? (t + 1) : t;
            const float* q0 = xp0 + (size_t)tn * 256;
            const float* q1 = xp1 + (size_t)tn * 256;
            #pragma unroll
            for (int g = 0; g < 4; g++) { xa[g] = q0[g * 64]; xb[g] = q1[g * 64]; }
        }
        __syncthreads();
    }

    // ========== epilogue: G1(TT-1) + PW1(TT-1) ==========
    {
        float g1a[4] = {0.f,0.f,0.f,0.f}, g1b[4] = {0.f,0.f,0.f,0.f};
        #pragma unroll
        for (int kt = 0; kt < 8; kt++) {
            const char* Ab = (kt < 4) ? (H0F + kt * 512) : (H1F + (kt - 4) * 512);
            uint4 Ah = *(const uint4*)(Ab + aoff);
            uint4 Al = *(const uint4*)(Ab + 2048 + aoff);
            uint2 C0 = *(const uint2*)(W1F + b1lo + kt * 256);
            uint2 C1 = *(const uint2*)(W1F + b1hi + kt * 256);
            mma_fp16(g1a, Ah, C0.x, C0.y);
            mma_fp16(g1a, Al, C0.x, C0.y);
            mma_fp16(g1b, Ah, C1.x, C1.y);
            mma_fp16(g1b, Al, C1.x, C1.y);
        }
        *(float2*)(gt1 + gwo0)     = make_float2(g1a[0], g1a[1]);
        *(float2*)(gt1 + gwo1)     = make_float2(g1a[2], g1a[3]);
        *(float2*)(gt1 + gwo0 + 8) = make_float2(g1b[0], g1b[1]);
        *(float2*)(gt1 + gwo1 + 8) = make_float2(g1b[2], g1b[3]);
    }
    __syncthreads();
    {
        float qi0 = bv.x + gt1[gr0],       qi1 = bv.x + gt1[gr1];
        float qf0 = bv.y + gt1[gr0 + 64],  qf1 = bv.y + gt1[gr1 + 64];
        float qg0 = bv.z + gt1[gr0 + 128], qg1 = bv.z + gt1[gr1 + 128];
        float qo0 = bv.w + gt1[gr0 + 192], qo1 = bv.w + gt1[gr1 + 192];
        c1a = sigf(qf0) * c1a + sigf(qi0) * tanhf_fast(qg0);
        c1b = sigf(qf1) * c1b + sigf(qi1) * tanhf_fast(qg1);
        gt0[gr0] = sigf(qo0) * tanhf_fast(c1a);   // final h1 (fp32) for FC
        gt0[gr1] = sigf(qo1) * tanhf_fast(c1b);
    }
    __syncthreads();

    // ---- FC head ----
    for (int idx = tid; idx < 16 * OO; idx += 512) {
        int o = idx / 16, r = idx & 15;
        float s = fc_b[o];
        #pragma unroll 8
        for (int k = 0; k < HH; k++)
            s += fc_w[o * HH + k] * gt0[r * 260 + k];
        out[(size_t)(bR0 + r) * OO + o] = s;
    }
}

// =====================================================================
extern "C" void kernel_launch(void* const* d_in, const int* in_sizes, int n_in,
                              void* d_out, int out_size)
{
    (void)in_sizes; (void)n_in; (void)out_size;
    const float* x     = (const float*)d_in[0];
    const float* w_ih0 = (const float*)d_in[1];
    const float* w_hh0 = (const float*)d_in[2];
    const float* b_ih0 = (const float*)d_in[3];
    const float* b_hh0 = (const float*)d_in[4];
    const float* w_ih1 = (const float*)d_in[5];
    const float* w_hh1 = (const float*)d_in[6];
    const float* b_ih1 = (const float*)d_in[7];
    const float* b_hh1 = (const float*)d_in[8];
    const float* fc_w  = (const float*)d_in[9];
    const float* fc_b  = (const float*)d_in[10];
    float* out = (float*)d_out;

    cudaFuncSetAttribute(k1_gemm, cudaFuncAttributeMaxDynamicSharedMemorySize, K1T_SMEM);
    cudaFuncSetAttribute(k2_rnn,  cudaFuncAttributeMaxDynamicSharedMemorySize, K2_SMEM);

    k1_gemm<<<(BB * TT) / (128 * K1T_TILES), 1024, K1T_SMEM>>>(x, w_ih0, b_ih0, b_hh0);
    k2_rnn<<<BB / 16, 512, K2_SMEM>>>(w_hh0, w_ih1, w_hh1, b_ih1, b_hh1,
                                      fc_w, fc_b, out);
}